// round 4
// baseline (speedup 1.0000x reference)
#include <cuda_runtime.h>
#include <math.h>
#include <stdint.h>

// Problem constants
#define BB   32
#define NN   64
#define NH   16
#define RR   1024
#define REP  1024
#define MM   1008
#define NCLS 117

// Output layout offsets (floats)
#define OFF_BH  66060288L
#define OFF_BO  66189312L
#define OFF_PR  66318336L

// ---------------- scratch (device globals) -----------------------------------
__device__ float g_encA[BB * NN * RR];
__device__ float g_encB[BB * NN * RR];
__device__ float g_UV [BB * NN * 2048];
__device__ float g_O  [BB * NN * REP];
__device__ float g_mh [BB * NH * REP];
__device__ float g_eh [BB * NH * RR];
__device__ float g_S  [BB * NH * REP];
__device__ float g_mo [BB * NN * REP];
__device__ float g_A  [BB * NH * NN];

// pre-split (hi,lo interleaved) weights
__device__ float g_W1s [2L * 1024 * 2048];   // fused UV weight: K=1024, N=2048
__device__ float g_W2s [2L * 1024 * 512];
__device__ float g_Wos [2L * 1024 * 1024];
__device__ float g_Wss [2L * 1024 * 1024];
__device__ float g_Wsus[2L * 2048 * 1024];
__device__ float g_Wous[2L * 2048 * 1024];

// ---------------- helpers ----------------------------------------------------
__device__ __forceinline__ void mma8(float* c, const uint32_t* a, const uint32_t* b)
{
    asm volatile(
        "mma.sync.aligned.m16n8k8.row.col.f32.tf32.tf32.f32 "
        "{%0,%1,%2,%3}, {%4,%5,%6,%7}, {%8,%9}, {%0,%1,%2,%3};\n"
        : "+f"(c[0]), "+f"(c[1]), "+f"(c[2]), "+f"(c[3])
        : "r"(a[0]), "r"(a[1]), "r"(a[2]), "r"(a[3]), "r"(b[0]), "r"(b[1]));
}

__device__ __forceinline__ void split2(float x, uint32_t& hi, uint32_t& lo)
{
    uint32_t h = __float_as_uint(x) & 0xffffe000u;
    hi = h;
    float l = x - __uint_as_float(h);
    lo = __float_as_uint(l) & 0xffffe000u;
}

__device__ __forceinline__ void cpa16(void* smem, const void* gmem)
{
    uint32_t s = (uint32_t)__cvta_generic_to_shared(smem);
    asm volatile("cp.async.cg.shared.global [%0], [%1], 16;\n" :: "r"(s), "l"(gmem));
}
__device__ __forceinline__ void cp_commit()
{
    asm volatile("cp.async.commit_group;\n");
}
template <int N> __device__ __forceinline__ void cp_wait()
{
    asm volatile("cp.async.wait_group %0;\n" :: "n"(N));
}

// ---------------- weight splitters -------------------------------------------
__global__ __launch_bounds__(256) void split_w(
    const float4* __restrict__ src, float4* __restrict__ dst, int n4)
{
    for (int i = blockIdx.x * blockDim.x + threadIdx.x; i < n4;
         i += gridDim.x * blockDim.x) {
        float4 x = src[i];
        uint32_t h, l;
        float4 o0, o1;
        split2(x.x, h, l); o0.x = __uint_as_float(h); o0.y = __uint_as_float(l);
        split2(x.y, h, l); o0.z = __uint_as_float(h); o0.w = __uint_as_float(l);
        split2(x.z, h, l); o1.x = __uint_as_float(h); o1.y = __uint_as_float(l);
        split2(x.w, h, l); o1.z = __uint_as_float(h); o1.w = __uint_as_float(l);
        dst[2 * i]     = o0;
        dst[2 * i + 1] = o1;
    }
}

// W1 is [2048, 1024]. Build fused Wuv: [1024 k][2048 n] where
// Wuv[k][c] = W1[k][c] (c<1024) else W1[1024+k][c-1024]; store split pairs.
__global__ __launch_bounds__(256) void split_w1(
    const float* __restrict__ W1, float* __restrict__ dst)
{
    for (long i = blockIdx.x * blockDim.x + threadIdx.x; i < 1024L * 2048;
         i += (long)gridDim.x * blockDim.x) {
        int k = (int)(i >> 11), c = (int)(i & 2047);
        float x = (c < 1024) ? W1[(long)k * 1024 + c]
                             : W1[(long)(1024 + k) * 1024 + (c - 1024)];
        uint32_t h, l;
        split2(x, h, l);
        dst[2 * i]     = __uint_as_float(h);
        dst[2 * i + 1] = __uint_as_float(l);
    }
}

// ---------------- batched GEMM (3xTF32, pre-split W, cp.async pipeline) ------
#define GEMM_SMEM ((2 * 64 * 36 + 2 * 32 * 272) * 4)
__global__ __launch_bounds__(256, 2) void gemm_tf32(
    const float* __restrict__ A1, int lrpb, long sA1, int K1,
    const float* __restrict__ A2, long sA2,
    const float* __restrict__ Wsp, const float* __restrict__ bias,
    float* __restrict__ C, int ldw2, int ldc, int Ktot, int do_relu)
{
    extern __shared__ __align__(16) float sm[];
    float* Asr = sm;               // [2][64][36] raw fp32
    float* Bs  = sm + 2 * 2304;    // [2][32][272] split pairs

    const int t = threadIdx.x, lane = t & 31, warp = t >> 5;
    const int gid = lane >> 2, tig = lane & 3;
    const int wm = warp >> 2, wn = warp & 3;
    const int m0 = wm * 32, n0w = wn * 32;
    const long bn0 = (long)blockIdx.x * 128;
    const int bm0 = blockIdx.y * 64;
    const int K2 = Ktot - K1;
    const int rmask = (1 << lrpb) - 1;

    const int lrow = t >> 3, lk4 = (t & 7) * 4;
    const float* p1[2];
    const float* p2[2];
#pragma unroll
    for (int i = 0; i < 2; i++) {
        int grow = bm0 + lrow + 32 * i;
        int b = grow >> lrpb, n = grow & rmask;
        p1[i] = A1 + (long)b * sA1 + (long)n * K1;
        p2[i] = A2 ? (A2 + (long)b * sA2 + (long)n * K2) : p1[i];
    }

    float c[2][4][4];
#pragma unroll
    for (int mt = 0; mt < 2; mt++)
#pragma unroll
        for (int nt = 0; nt < 4; nt++)
#pragma unroll
            for (int e = 0; e < 4; e++) c[mt][nt][e] = 0.f;

    auto stage = [&](int buf, int k0) {
#pragma unroll
        for (int i = 0; i < 2; i++) {
            const float* src = (k0 < K1) ? (p1[i] + k0 + lk4)
                                         : (p2[i] + (k0 - K1) + lk4);
            cpa16(&Asr[buf * 2304 + (lrow + 32 * i) * 36 + lk4], src);
        }
#pragma unroll
        for (int i = 0; i < 8; i++) {
            int f = t + i * 256;
            int kk = f >> 6, q = (f & 63) * 4;
            cpa16(&Bs[buf * 8704 + kk * 272 + q],
                  Wsp + (long)(k0 + kk) * ldw2 + bn0 * 2 + q);
        }
        cp_commit();
    };

    stage(0, 0);
    int buf = 0;
    for (int k0 = 0; k0 < Ktot; k0 += 32) {
        const bool more = (k0 + 32 < Ktot);
        if (more) stage(buf ^ 1, k0 + 32);
        if (more) cp_wait<1>(); else cp_wait<0>();
        __syncthreads();

        const float* Ab = &Asr[buf * 2304];
        const float* Bb = &Bs[buf * 8704];
#pragma unroll
        for (int k8 = 0; k8 < 4; k8++) {
            const int kb = k8 * 8;
            uint32_t ah[2][4], al[2][4];
#pragma unroll
            for (int mt = 0; mt < 2; mt++) {
                int r = m0 + mt * 16 + gid;
                split2(Ab[r * 36 + kb + tig],           ah[mt][0], al[mt][0]);
                split2(Ab[(r + 8) * 36 + kb + tig],     ah[mt][1], al[mt][1]);
                split2(Ab[r * 36 + kb + tig + 4],       ah[mt][2], al[mt][2]);
                split2(Ab[(r + 8) * 36 + kb + tig + 4], ah[mt][3], al[mt][3]);
            }
#pragma unroll
            for (int nt = 0; nt < 4; nt++) {
                int cn = n0w + nt * 8 + gid;
                float2 b0 = *(const float2*)&Bb[(kb + tig) * 272 + 2 * cn];
                float2 b1 = *(const float2*)&Bb[(kb + tig + 4) * 272 + 2 * cn];
                uint32_t bh[2] = { __float_as_uint(b0.x), __float_as_uint(b1.x) };
                uint32_t bl[2] = { __float_as_uint(b0.y), __float_as_uint(b1.y) };
#pragma unroll
                for (int mt = 0; mt < 2; mt++) {
                    mma8(c[mt][nt], ah[mt], bh);
                    mma8(c[mt][nt], ah[mt], bl);
                    mma8(c[mt][nt], al[mt], bh);
                }
            }
        }
        __syncthreads();
        buf ^= 1;
    }

#pragma unroll
    for (int mt = 0; mt < 2; mt++) {
#pragma unroll
        for (int nt = 0; nt < 4; nt++) {
            long col = bn0 + n0w + nt * 8 + 2 * tig;
            float b0v = 0.f, b1v = 0.f;
            if (bias) { b0v = bias[col]; b1v = bias[col + 1]; }
            int r = bm0 + m0 + mt * 16 + gid;
            float v0 = c[mt][nt][0] + b0v, v1 = c[mt][nt][1] + b1v;
            float v2 = c[mt][nt][2] + b0v, v3 = c[mt][nt][3] + b1v;
            if (do_relu) {
                v0 = fmaxf(v0, 0.f); v1 = fmaxf(v1, 0.f);
                v2 = fmaxf(v2, 0.f); v3 = fmaxf(v3, 0.f);
            }
            *(float2*)&C[(long)r * ldc + col]       = make_float2(v0, v1);
            *(float2*)&C[(long)(r + 8) * ldc + col] = make_float2(v2, v3);
        }
    }
}

// ---------------- fused pair MLP (3xTF32, pre-split W2) ----------------------
#define PAIR_SMEM ((2 * 16 * 1040 + 2 * 64 * 36 + 64 * 8) * 4)
__global__ __launch_bounds__(512, 1) void pair_mlp_mma(
    const float* __restrict__ UV, const float* __restrict__ b1,
    const float* __restrict__ W2sp, const float* __restrict__ b2,
    const float* __restrict__ W3, const float* __restrict__ b3,
    float* __restrict__ Aout)
{
    extern __shared__ __align__(16) float sm[];
    float* Bs    = sm;                       // [2][16][1040] split pairs
    float* h1s   = sm + 2 * 16640;           // [2][64][36]  split pairs
    float* wpart = h1s + 2 * 2304;           // [64][8]

    const int t = threadIdx.x, lane = t & 31, warp = t >> 5;
    const int gid = lane >> 2, tig = lane & 3;
    const int wm = warp >> 3, wn = warp & 7;
    const int m0 = wm * 32, n0w = wn * 64;
    const int bi = blockIdx.y;

    const int lr = t >> 3, k2 = (t & 7) * 2;
    const int mld = blockIdx.x * 64 + lr;
    const int valid = (mld < MM);
    int xl = 0, yl = 0;
    if (valid) { xl = mld / 63; int rl = mld - 63 * xl; yl = rl + (rl >= xl ? 1 : 0); }
    const float* Urow = UV + ((long)(bi * 64 + xl)) * 2048;
    const float* Vrow = UV + ((long)(bi * 64 + yl)) * 2048 + 1024;

    float c[2][8][4];
#pragma unroll
    for (int mt = 0; mt < 2; mt++)
#pragma unroll
        for (int nt = 0; nt < 8; nt++)
#pragma unroll
            for (int e = 0; e < 4; e++) c[mt][nt][e] = 0.f;

    auto stage = [&](int buf, int k0) {
        float2 u  = *(const float2*)(Urow + k0 + k2);
        float2 v  = *(const float2*)(Vrow + k0 + k2);
        float2 bb = *(const float2*)(b1 + k0 + k2);
        float h0 = fmaxf(u.x + v.x + bb.x, 0.f);
        float h1 = fmaxf(u.y + v.y + bb.y, 0.f);
        if (!valid) { h0 = 0.f; h1 = 0.f; }
        uint32_t hh, ll;
        float4 o;
        split2(h0, hh, ll); o.x = __uint_as_float(hh); o.y = __uint_as_float(ll);
        split2(h1, hh, ll); o.z = __uint_as_float(hh); o.w = __uint_as_float(ll);
        *(float4*)&h1s[buf * 2304 + lr * 36 + 2 * k2] = o;
#pragma unroll
        for (int i = 0; i < 8; i++) {
            int f = t + i * 512;
            int kk = f >> 8, q = (f & 255) * 4;
            cpa16(&Bs[buf * 16640 + kk * 1040 + q],
                  W2sp + (long)(k0 + kk) * 1024 + q);
        }
        cp_commit();
    };

    stage(0, 0);
    int buf = 0;
    for (int k0 = 0; k0 < REP; k0 += 16) {
        const bool more = (k0 + 16 < REP);
        if (more) stage(buf ^ 1, k0 + 16);
        if (more) cp_wait<1>(); else cp_wait<0>();
        __syncthreads();

        const float* Ab = &h1s[buf * 2304];
        const float* Bb = &Bs[buf * 16640];
#pragma unroll
        for (int k8 = 0; k8 < 2; k8++) {
            const int kb = k8 * 8;
            uint32_t ah[2][4], al[2][4];
#pragma unroll
            for (int mt = 0; mt < 2; mt++) {
                int r = m0 + mt * 16 + gid;
                float2 a0 = *(const float2*)&Ab[r * 36 + 2 * (kb + tig)];
                float2 a1 = *(const float2*)&Ab[(r + 8) * 36 + 2 * (kb + tig)];
                float2 a2 = *(const float2*)&Ab[r * 36 + 2 * (kb + tig + 4)];
                float2 a3 = *(const float2*)&Ab[(r + 8) * 36 + 2 * (kb + tig + 4)];
                ah[mt][0] = __float_as_uint(a0.x); al[mt][0] = __float_as_uint(a0.y);
                ah[mt][1] = __float_as_uint(a1.x); al[mt][1] = __float_as_uint(a1.y);
                ah[mt][2] = __float_as_uint(a2.x); al[mt][2] = __float_as_uint(a2.y);
                ah[mt][3] = __float_as_uint(a3.x); al[mt][3] = __float_as_uint(a3.y);
            }
#pragma unroll
            for (int nt = 0; nt < 8; nt++) {
                int cn = n0w + nt * 8 + gid;
                float2 b0 = *(const float2*)&Bb[(kb + tig) * 1040 + 2 * cn];
                float2 b1f = *(const float2*)&Bb[(kb + tig + 4) * 1040 + 2 * cn];
                uint32_t bh[2] = { __float_as_uint(b0.x), __float_as_uint(b1f.x) };
                uint32_t bl[2] = { __float_as_uint(b0.y), __float_as_uint(b1f.y) };
#pragma unroll
                for (int mt = 0; mt < 2; mt++) {
                    mma8(c[mt][nt], ah[mt], bh);
                    mma8(c[mt][nt], ah[mt], bl);
                    mma8(c[mt][nt], al[mt], bh);
                }
            }
        }
        __syncthreads();
        buf ^= 1;
    }

    float rp[4] = { 0.f, 0.f, 0.f, 0.f };
#pragma unroll
    for (int mt = 0; mt < 2; mt++) {
#pragma unroll
        for (int nt = 0; nt < 8; nt++) {
            int col = n0w + nt * 8 + 2 * tig;
            float b2a = b2[col], b2b = b2[col + 1];
            float w3a = W3[col], w3b = W3[col + 1];
            rp[2 * mt + 0] += fmaxf(c[mt][nt][0] + b2a, 0.f) * w3a
                            + fmaxf(c[mt][nt][1] + b2b, 0.f) * w3b;
            rp[2 * mt + 1] += fmaxf(c[mt][nt][2] + b2a, 0.f) * w3a
                            + fmaxf(c[mt][nt][3] + b2b, 0.f) * w3b;
        }
    }
#pragma unroll
    for (int e = 0; e < 4; e++) {
        float v = rp[e];
        v += __shfl_xor_sync(0xffffffffu, v, 1);
        v += __shfl_xor_sync(0xffffffffu, v, 2);
        int mt = e >> 1, o = e & 1;
        if (tig == 0) wpart[(m0 + mt * 16 + o * 8 + gid) * 8 + wn] = v;
    }
    __syncthreads();
    if (t < 64) {
        float s = b3[0];
#pragma unroll
        for (int w = 0; w < 8; w++) s += wpart[t * 8 + w];
        int m = blockIdx.x * 64 + t;
        if (m < MM) {
            int x = m / 63; int r = m - 63 * x; int y = r + (r >= x ? 1 : 0);
            Aout[(bi * 16 + x) * 64 + y] = 1.f / (1.f + expf(-s));
        }
    }
}

// ---------------- msg_h = A @ O ----------------------------------------------
__global__ __launch_bounds__(256) void msg_h_k(
    const float* __restrict__ Ag, const float* __restrict__ O, float* __restrict__ mh)
{
    __shared__ float As[NH * NN];
    const int b = blockIdx.y, t = threadIdx.x;
#pragma unroll
    for (int i = 0; i < 4; i++) As[t + 256 * i] = Ag[b * NH * NN + t + 256 * i];
    __syncthreads();
    const int j = blockIdx.x * 256 + t;
    float acc[NH];
#pragma unroll
    for (int x = 0; x < NH; x++) acc[x] = 0.f;
    for (int n = 0; n < NN; n++) {
        float o = O[((long)(b * NN + n)) * 1024 + j];
#pragma unroll
        for (int x = 0; x < NH; x++) acc[x] += As[x * NN + n] * o;
    }
#pragma unroll
    for (int x = 0; x < NH; x++) mh[((long)(b * NH + x)) * 1024 + j] = acc[x];
}

// ---------------- msg_o = A^T @ S --------------------------------------------
__global__ __launch_bounds__(256) void msg_o_k(
    const float* __restrict__ Ag, const float* __restrict__ Sm, float* __restrict__ mo)
{
    __shared__ float As[NH * NN];
    const int b = blockIdx.y, t = threadIdx.x;
#pragma unroll
    for (int i = 0; i < 4; i++) As[t + 256 * i] = Ag[b * NH * NN + t + 256 * i];
    __syncthreads();
    const int j = blockIdx.x * 256 + t;
    float s[NH];
#pragma unroll
    for (int x = 0; x < NH; x++) s[x] = Sm[((long)(b * NH + x)) * 1024 + j];
    for (int n = 0; n < NN; n++) {
        float acc = 0.f;
#pragma unroll
        for (int x = 0; x < NH; x++) acc += As[x * NN + n] * s[x];
        mo[((long)(b * NN + n)) * 1024 + j] = acc;
    }
}

// ---------------- output assembly --------------------------------------------
__device__ __forceinline__ float lis_f(float s) {
    return 8.3f / (1.f + expf(12.f - 10.f * s));
}

__global__ __launch_bounds__(128) void out_kernel(
    const float* __restrict__ enc, const float* __restrict__ Ag,
    const float* __restrict__ coords, const int* __restrict__ labels,
    const float* __restrict__ scores, float* __restrict__ out)
{
    const int b = blockIdx.y, m = blockIdx.x, t = threadIdx.x;
    const int x = m / 63; const int r = m - 63 * x; const int y = r + (r >= x ? 1 : 0);
    const long row = (long)b * MM + m;

    const float4* ex = (const float4*)(enc + ((long)(b * NN + x)) * RR);
    const float4* ey = (const float4*)(enc + ((long)(b * NN + y)) * RR);
    float4* po = (float4*)(out + row * 2048);
#pragma unroll
    for (int i = 0; i < 4; i++) {
        int q = t + (i << 7);
        po[q] = (q < 256) ? ex[q] : ey[q - 256];
    }
    if (t < 4)        out[OFF_BH + row * 4 + t]       = coords[(b * NN + x) * 4 + t];
    else if (t < 8)   out[OFF_BO + row * 4 + (t - 4)] = coords[(b * NN + y) * 4 + (t - 4)];

    const int lbl = labels[b * NN + y];
    const float val = Ag[(b * NH + x) * NN + y] *
                      lis_f(scores[b * NN + x]) * lis_f(scores[b * NN + y]);
    for (int c = t; c < NCLS; c += 128)
        out[OFF_PR + row * (long)NCLS + c] = (c == lbl) ? val : 0.f;
}

// ---------------- host orchestration -----------------------------------------
extern "C" void kernel_launch(void* const* d_in, const int* in_sizes, int n_in,
                              void* d_out, int out_size)
{
    const float* box_features = (const float*)d_in[0];
    const float* box_coords   = (const float*)d_in[1];
    const int*   box_labels   = (const int*)  d_in[2];
    const float* box_scores   = (const float*)d_in[3];
    const float* W1  = (const float*)d_in[4];
    const float* b1  = (const float*)d_in[5];
    const float* W2  = (const float*)d_in[6];
    const float* b2  = (const float*)d_in[7];
    const float* W3  = (const float*)d_in[8];
    const float* b3  = (const float*)d_in[9];
    const float* Ws  = (const float*)d_in[10];
    const float* bs  = (const float*)d_in[11];
    const float* Wo  = (const float*)d_in[12];
    const float* bo  = (const float*)d_in[13];
    const float* Wsu = (const float*)d_in[14];
    const float* Wou = (const float*)d_in[15];
    float* out = (float*)d_out;

    float *encA, *encB, *UV, *O, *mh, *eh, *Sb, *mo, *Ag;
    float *W1s, *W2s, *Wos, *Wss, *Wsus, *Wous;
    cudaGetSymbolAddress((void**)&encA, g_encA);
    cudaGetSymbolAddress((void**)&encB, g_encB);
    cudaGetSymbolAddress((void**)&UV,   g_UV);
    cudaGetSymbolAddress((void**)&O,    g_O);
    cudaGetSymbolAddress((void**)&mh,   g_mh);
    cudaGetSymbolAddress((void**)&eh,   g_eh);
    cudaGetSymbolAddress((void**)&Sb,   g_S);
    cudaGetSymbolAddress((void**)&mo,   g_mo);
    cudaGetSymbolAddress((void**)&Ag,   g_A);
    cudaGetSymbolAddress((void**)&W1s,  g_W1s);
    cudaGetSymbolAddress((void**)&W2s,  g_W2s);
    cudaGetSymbolAddress((void**)&Wos,  g_Wos);
    cudaGetSymbolAddress((void**)&Wss,  g_Wss);
    cudaGetSymbolAddress((void**)&Wsus, g_Wsus);
    cudaGetSymbolAddress((void**)&Wous, g_Wous);

    cudaFuncSetAttribute(gemm_tf32,
                         cudaFuncAttributeMaxDynamicSharedMemorySize, GEMM_SMEM);
    cudaFuncSetAttribute(pair_mlp_mma,
                         cudaFuncAttributeMaxDynamicSharedMemorySize, PAIR_SMEM);

    // pre-split all weights; W1 gets the fused/rearranged UV layout
    split_w1<<<512, 256>>>(W1, W1s);
    split_w<<<512, 256>>>((const float4*)W2,  (float4*)W2s,  (1024 * 512) / 4);
    split_w<<<512, 256>>>((const float4*)Wo,  (float4*)Wos,  (1024 * 1024) / 4);
    split_w<<<512, 256>>>((const float4*)Ws,  (float4*)Wss,  (1024 * 1024) / 4);
    split_w<<<512, 256>>>((const float4*)Wsu, (float4*)Wsus, (2048 * 1024) / 4);
    split_w<<<512, 256>>>((const float4*)Wou, (float4*)Wous, (2048 * 1024) / 4);

    cudaMemcpyAsync(encA, box_features, (size_t)BB * NN * RR * 4,
                    cudaMemcpyDeviceToDevice, 0);

    const long sEnc = (long)NN * RR;   // 65536
    const long sH   = (long)NH * RR;   // 16384

    for (int it = 0; it < 2; it++) {
        float* encIn  = (it == 0) ? encA : encB;
        float* encOut = (it == 0) ? encB : encA;

        // UV = enc @ Wuv  (K=1024, N=2048)
        gemm_tf32<<<dim3(16, 32), 256, GEMM_SMEM>>>(
            encIn, 6, sEnc, 1024, (const float*)0, 0,
            W1s, (const float*)0, UV, 4096, 2048, 1024, 0);
        // A = sigmoid(pair MLP)
        pair_mlp_mma<<<dim3(16, BB), 512, PAIR_SMEM>>>(
            UV, b1, W2s, b2, W3, b3, Ag);
        // O = relu(enc @ Wo + bo)
        gemm_tf32<<<dim3(8, 32), 256, GEMM_SMEM>>>(
            encIn, 6, sEnc, 1024, (const float*)0, 0,
            Wos, bo, O, 2048, 1024, 1024, 1);
        // msg_h = A @ O
        msg_h_k<<<dim3(4, BB), 256>>>(Ag, O, mh);
        // enc_h = concat(enc[:16], msg_h) @ Wsu
        gemm_tf32<<<dim3(8, 8), 256, GEMM_SMEM>>>(
            encIn, 4, sEnc, 1024, mh, sH,
            Wsus, (const float*)0, eh, 2048, 1024, 2048, 0);
        // enc[:16] = enc_h
        cudaMemcpy2DAsync(encIn, (size_t)sEnc * 4, eh, (size_t)sH * 4,
                          (size_t)sH * 4, BB, cudaMemcpyDeviceToDevice, 0);
        // S = relu(enc_h @ Ws + bs)
        gemm_tf32<<<dim3(8, 8), 256, GEMM_SMEM>>>(
            eh, 4, sH, 1024, (const float*)0, 0,
            Wss, bs, Sb, 2048, 1024, 1024, 1);
        // msg_o = A^T @ S
        msg_o_k<<<dim3(4, BB), 256>>>(Ag, Sb, mo);
        // encOut = concat(enc, msg_o) @ Wou
        gemm_tf32<<<dim3(8, 32), 256, GEMM_SMEM>>>(
            encIn, 6, sEnc, 1024, mo, sEnc,
            Wous, (const float*)0, encOut, 2048, 1024, 2048, 0);
    }

    out_kernel<<<dim3(MM, BB), 128>>>(encA, Ag, box_coords, box_labels,
                                      box_scores, out);
    (void)in_sizes; (void)n_in; (void)out_size;
}

// round 5
// speedup vs baseline: 1.3025x; 1.3025x over previous
#include <cuda_runtime.h>
#include <math.h>
#include <stdint.h>

// Problem constants
#define BB   32
#define NN   64
#define NH   16
#define RR   1024
#define REP  1024
#define MM   1008
#define NCLS 117

// Output layout offsets (floats)
#define OFF_BH  66060288L
#define OFF_BO  66189312L
#define OFF_PR  66318336L

// ---------------- scratch (device globals) -----------------------------------
__device__ float g_encA[BB * NN * RR];
__device__ float g_encB[BB * NN * RR];
__device__ float g_UV [BB * NN * 2048];
__device__ float g_O  [BB * NN * REP];
__device__ float g_mh [BB * NH * REP];
__device__ float g_eh [BB * NH * RR];
__device__ float g_S  [BB * NH * REP];
__device__ float g_mo [BB * NN * REP];
__device__ float g_A  [BB * NH * NN];
__device__ float g_Wuv[1024L * 2048];   // fused UV weight (raw): K=1024, N=2048

// ---------------- helpers ----------------------------------------------------
__device__ __forceinline__ void mma8(float* c, const uint32_t* a, const uint32_t* b)
{
    asm volatile(
        "mma.sync.aligned.m16n8k8.row.col.f32.tf32.tf32.f32 "
        "{%0,%1,%2,%3}, {%4,%5,%6,%7}, {%8,%9}, {%0,%1,%2,%3};\n"
        : "+f"(c[0]), "+f"(c[1]), "+f"(c[2]), "+f"(c[3])
        : "r"(a[0]), "r"(a[1]), "r"(a[2]), "r"(a[3]), "r"(b[0]), "r"(b[1]));
}

__device__ __forceinline__ void split2(float x, uint32_t& hi, uint32_t& lo)
{
    uint32_t h = __float_as_uint(x) & 0xffffe000u;
    hi = h;
    float l = x - __uint_as_float(h);
    lo = __float_as_uint(l) & 0xffffe000u;
}

__device__ __forceinline__ void cpa16(void* smem, const void* gmem)
{
    uint32_t s = (uint32_t)__cvta_generic_to_shared(smem);
    asm volatile("cp.async.cg.shared.global [%0], [%1], 16;\n" :: "r"(s), "l"(gmem));
}
__device__ __forceinline__ void cp_commit()
{
    asm volatile("cp.async.commit_group;\n");
}
template <int N> __device__ __forceinline__ void cp_wait()
{
    asm volatile("cp.async.wait_group %0;\n" :: "n"(N));
}

// ---------------- build fused Wuv (raw) --------------------------------------
// W1 is [2048, 1024]. Wuv[k][c] = W1[k][c] (c<1024) else W1[1024+k][c-1024].
__global__ __launch_bounds__(256) void fuse_w1(
    const float* __restrict__ W1, float* __restrict__ dst)
{
    for (long i = blockIdx.x * blockDim.x + threadIdx.x; i < 1024L * 2048;
         i += (long)gridDim.x * blockDim.x) {
        int k = (int)(i >> 11), c = (int)(i & 2047);
        dst[i] = (c < 1024) ? W1[(long)k * 1024 + c]
                            : W1[(long)(1024 + k) * 1024 + (c - 1024)];
    }
}

// ---------------- batched GEMM (3xTF32, raw smem, cp.async 2-stage) ----------
// A flat row r -> (b = r>>lrpb, n = r&mask); optional K-concat A2.
// W raw row-major [Ktot, ldw]. C flat [.,ldc]. BM=64, BN=128, BK=32, 256 thr.
#define GEMM_SMEM ((2 * 64 * 36 + 2 * 32 * 136) * 4)
__global__ __launch_bounds__(256, 2) void gemm_tf32(
    const float* __restrict__ A1, int lrpb, long sA1, int K1,
    const float* __restrict__ A2, long sA2,
    const float* __restrict__ W, const float* __restrict__ bias,
    float* __restrict__ C, int ldw, int ldc, int Ktot, int do_relu)
{
    extern __shared__ __align__(16) float sm[];
    float* Asr = sm;               // [2][64][36] raw
    float* Bs  = sm + 2 * 2304;    // [2][32][136] raw

    const int t = threadIdx.x, lane = t & 31, warp = t >> 5;
    const int gid = lane >> 2, tig = lane & 3;
    const int wm = warp >> 2, wn = warp & 3;
    const int m0 = wm * 32, n0w = wn * 32;
    const long bn0 = (long)blockIdx.x * 128;
    const int bm0 = blockIdx.y * 64;
    const int K2 = Ktot - K1;
    const int rmask = (1 << lrpb) - 1;

    const int lrow = t >> 3, lk4 = (t & 7) * 4;
    const float* p1[2];
    const float* p2[2];
#pragma unroll
    for (int i = 0; i < 2; i++) {
        int grow = bm0 + lrow + 32 * i;
        int b = grow >> lrpb, n = grow & rmask;
        p1[i] = A1 + (long)b * sA1 + (long)n * K1;
        p2[i] = A2 ? (A2 + (long)b * sA2 + (long)n * K2) : p1[i];
    }

    float c[2][4][4];
#pragma unroll
    for (int mt = 0; mt < 2; mt++)
#pragma unroll
        for (int nt = 0; nt < 4; nt++)
#pragma unroll
            for (int e = 0; e < 4; e++) c[mt][nt][e] = 0.f;

    auto stage = [&](int buf, int k0) {
#pragma unroll
        for (int i = 0; i < 2; i++) {
            const float* src = (k0 < K1) ? (p1[i] + k0 + lk4)
                                         : (p2[i] + (k0 - K1) + lk4);
            cpa16(&Asr[buf * 2304 + (lrow + 32 * i) * 36 + lk4], src);
        }
#pragma unroll
        for (int i = 0; i < 4; i++) {
            int f = t + i * 256;
            int kk = f >> 5, n4 = (f & 31) * 4;
            cpa16(&Bs[buf * 4352 + kk * 136 + n4],
                  W + (long)(k0 + kk) * ldw + bn0 + n4);
        }
        cp_commit();
    };

    stage(0, 0);
    int buf = 0;
    for (int k0 = 0; k0 < Ktot; k0 += 32) {
        const bool more = (k0 + 32 < Ktot);
        if (more) stage(buf ^ 1, k0 + 32);
        if (more) cp_wait<1>(); else cp_wait<0>();
        __syncthreads();

        const float* Ab = &Asr[buf * 2304];
        const float* Bb = &Bs[buf * 4352];
#pragma unroll
        for (int k8 = 0; k8 < 4; k8++) {
            const int kb = k8 * 8;
            uint32_t ah[2][4], al[2][4];
#pragma unroll
            for (int mt = 0; mt < 2; mt++) {
                int r = m0 + mt * 16 + gid;
                split2(Ab[r * 36 + kb + tig],           ah[mt][0], al[mt][0]);
                split2(Ab[(r + 8) * 36 + kb + tig],     ah[mt][1], al[mt][1]);
                split2(Ab[r * 36 + kb + tig + 4],       ah[mt][2], al[mt][2]);
                split2(Ab[(r + 8) * 36 + kb + tig + 4], ah[mt][3], al[mt][3]);
            }
#pragma unroll
            for (int nt = 0; nt < 4; nt++) {
                int cn = n0w + nt * 8 + gid;
                uint32_t bh[2], bl[2];
                split2(Bb[(kb + tig) * 136 + cn],     bh[0], bl[0]);
                split2(Bb[(kb + tig + 4) * 136 + cn], bh[1], bl[1]);
#pragma unroll
                for (int mt = 0; mt < 2; mt++) {
                    mma8(c[mt][nt], ah[mt], bh);
                    mma8(c[mt][nt], ah[mt], bl);
                    mma8(c[mt][nt], al[mt], bh);
                }
            }
        }
        __syncthreads();
        buf ^= 1;
    }

#pragma unroll
    for (int mt = 0; mt < 2; mt++) {
#pragma unroll
        for (int nt = 0; nt < 4; nt++) {
            long col = bn0 + n0w + nt * 8 + 2 * tig;
            float b0v = 0.f, b1v = 0.f;
            if (bias) { b0v = bias[col]; b1v = bias[col + 1]; }
            int r = bm0 + m0 + mt * 16 + gid;
            float v0 = c[mt][nt][0] + b0v, v1 = c[mt][nt][1] + b1v;
            float v2 = c[mt][nt][2] + b0v, v3 = c[mt][nt][3] + b1v;
            if (do_relu) {
                v0 = fmaxf(v0, 0.f); v1 = fmaxf(v1, 0.f);
                v2 = fmaxf(v2, 0.f); v3 = fmaxf(v3, 0.f);
            }
            *(float2*)&C[(long)r * ldc + col]       = make_float2(v0, v1);
            *(float2*)&C[(long)(r + 8) * ldc + col] = make_float2(v2, v3);
        }
    }
}

// ---------------- fused pair MLP (3xTF32, raw W2, cp.async 2-stage) ----------
// BM=64 pairs, BN=512 (full width), BK=32, 512 threads. grid (16, 32).
#define PAIR_SMEM ((2 * 64 * 36 + 2 * 32 * 520 + 64 * 8) * 4)
__global__ __launch_bounds__(512, 1) void pair_mlp_mma(
    const float* __restrict__ UV, const float* __restrict__ b1,
    const float* __restrict__ W2, const float* __restrict__ b2,
    const float* __restrict__ W3, const float* __restrict__ b3,
    float* __restrict__ Aout)
{
    extern __shared__ __align__(16) float sm[];
    float* h1s   = sm;                       // [2][64][36] raw
    float* Bs    = sm + 2 * 2304;            // [2][32][520] raw
    float* wpart = sm + 2 * 2304 + 2 * 16640; // [64][8]

    const int t = threadIdx.x, lane = t & 31, warp = t >> 5;
    const int gid = lane >> 2, tig = lane & 3;
    const int wm = warp >> 3, wn = warp & 7;
    const int m0 = wm * 32, n0w = wn * 64;
    const int bi = blockIdx.y;

    // h1 loader role: one float4 of k per thread per stage
    const int lr = t >> 3, k4 = (t & 7) * 4;
    const int mld = blockIdx.x * 64 + lr;
    const int valid = (mld < MM);
    int xl = 0, yl = 0;
    if (valid) { xl = mld / 63; int rl = mld - 63 * xl; yl = rl + (rl >= xl ? 1 : 0); }
    const float* Urow = UV + ((long)(bi * 64 + xl)) * 2048;
    const float* Vrow = UV + ((long)(bi * 64 + yl)) * 2048 + 1024;

    float c[2][8][4];
#pragma unroll
    for (int mt = 0; mt < 2; mt++)
#pragma unroll
        for (int nt = 0; nt < 8; nt++)
#pragma unroll
            for (int e = 0; e < 4; e++) c[mt][nt][e] = 0.f;

    auto stage = [&](int buf, int k0) {
        // h1 tile
        float4 u  = *(const float4*)(Urow + k0 + k4);
        float4 v  = *(const float4*)(Vrow + k0 + k4);
        float4 bb = *(const float4*)(b1 + k0 + k4);
        float4 h;
        h.x = fmaxf(u.x + v.x + bb.x, 0.f);
        h.y = fmaxf(u.y + v.y + bb.y, 0.f);
        h.z = fmaxf(u.z + v.z + bb.z, 0.f);
        h.w = fmaxf(u.w + v.w + bb.w, 0.f);
        if (!valid) h = make_float4(0.f, 0.f, 0.f, 0.f);
        *(float4*)&h1s[buf * 2304 + lr * 36 + k4] = h;
        // W2 slab [32][512] raw via cp.async
#pragma unroll
        for (int i = 0; i < 8; i++) {
            int f = t + i * 512;
            int kk = f >> 7, n4 = (f & 127) * 4;
            cpa16(&Bs[buf * 16640 + kk * 520 + n4],
                  W2 + (long)(k0 + kk) * 512 + n4);
        }
        cp_commit();
    };

    stage(0, 0);
    int buf = 0;
    for (int k0 = 0; k0 < REP; k0 += 32) {
        const bool more = (k0 + 32 < REP);
        if (more) stage(buf ^ 1, k0 + 32);
        if (more) cp_wait<1>(); else cp_wait<0>();
        __syncthreads();

        const float* Ab = &h1s[buf * 2304];
        const float* Bb = &Bs[buf * 16640];
#pragma unroll
        for (int k8 = 0; k8 < 4; k8++) {
            const int kb = k8 * 8;
            uint32_t ah[2][4], al[2][4];
#pragma unroll
            for (int mt = 0; mt < 2; mt++) {
                int r = m0 + mt * 16 + gid;
                split2(Ab[r * 36 + kb + tig],           ah[mt][0], al[mt][0]);
                split2(Ab[(r + 8) * 36 + kb + tig],     ah[mt][1], al[mt][1]);
                split2(Ab[r * 36 + kb + tig + 4],       ah[mt][2], al[mt][2]);
                split2(Ab[(r + 8) * 36 + kb + tig + 4], ah[mt][3], al[mt][3]);
            }
#pragma unroll
            for (int nt = 0; nt < 8; nt++) {
                int cn = n0w + nt * 8 + gid;
                uint32_t bh[2], bl[2];
                split2(Bb[(kb + tig) * 520 + cn],     bh[0], bl[0]);
                split2(Bb[(kb + tig + 4) * 520 + cn], bh[1], bl[1]);
#pragma unroll
                for (int mt = 0; mt < 2; mt++) {
                    mma8(c[mt][nt], ah[mt], bh);
                    mma8(c[mt][nt], ah[mt], bl);
                    mma8(c[mt][nt], al[mt], bh);
                }
            }
        }
        __syncthreads();
        buf ^= 1;
    }

    // epilogue: h2 = relu(c + b2); partial w = h2 @ W3
    float rp[4] = { 0.f, 0.f, 0.f, 0.f };
#pragma unroll
    for (int mt = 0; mt < 2; mt++) {
#pragma unroll
        for (int nt = 0; nt < 8; nt++) {
            int col = n0w + nt * 8 + 2 * tig;
            float b2a = b2[col], b2b = b2[col + 1];
            float w3a = W3[col], w3b = W3[col + 1];
            rp[2 * mt + 0] += fmaxf(c[mt][nt][0] + b2a, 0.f) * w3a
                            + fmaxf(c[mt][nt][1] + b2b, 0.f) * w3b;
            rp[2 * mt + 1] += fmaxf(c[mt][nt][2] + b2a, 0.f) * w3a
                            + fmaxf(c[mt][nt][3] + b2b, 0.f) * w3b;
        }
    }
#pragma unroll
    for (int e = 0; e < 4; e++) {
        float v = rp[e];
        v += __shfl_xor_sync(0xffffffffu, v, 1);
        v += __shfl_xor_sync(0xffffffffu, v, 2);
        int mt = e >> 1, o = e & 1;
        if (tig == 0) wpart[(m0 + mt * 16 + o * 8 + gid) * 8 + wn] = v;
    }
    __syncthreads();
    if (t < 64) {
        float s = b3[0];
#pragma unroll
        for (int w = 0; w < 8; w++) s += wpart[t * 8 + w];
        int m = blockIdx.x * 64 + t;
        if (m < MM) {
            int x = m / 63; int r = m - 63 * x; int y = r + (r >= x ? 1 : 0);
            Aout[(bi * 16 + x) * 64 + y] = 1.f / (1.f + expf(-s));
        }
    }
}

// ---------------- msg_h = A @ O ----------------------------------------------
__global__ __launch_bounds__(256) void msg_h_k(
    const float* __restrict__ Ag, const float* __restrict__ O, float* __restrict__ mh)
{
    __shared__ float As[NH * NN];
    const int b = blockIdx.y, t = threadIdx.x;
#pragma unroll
    for (int i = 0; i < 4; i++) As[t + 256 * i] = Ag[b * NH * NN + t + 256 * i];
    __syncthreads();
    const int j = blockIdx.x * 256 + t;
    float acc[NH];
#pragma unroll
    for (int x = 0; x < NH; x++) acc[x] = 0.f;
    for (int n = 0; n < NN; n++) {
        float o = O[((long)(b * NN + n)) * 1024 + j];
#pragma unroll
        for (int x = 0; x < NH; x++) acc[x] += As[x * NN + n] * o;
    }
#pragma unroll
    for (int x = 0; x < NH; x++) mh[((long)(b * NH + x)) * 1024 + j] = acc[x];
}

// ---------------- msg_o = A^T @ S --------------------------------------------
__global__ __launch_bounds__(256) void msg_o_k(
    const float* __restrict__ Ag, const float* __restrict__ Sm, float* __restrict__ mo)
{
    __shared__ float As[NH * NN];
    const int b = blockIdx.y, t = threadIdx.x;
#pragma unroll
    for (int i = 0; i < 4; i++) As[t + 256 * i] = Ag[b * NH * NN + t + 256 * i];
    __syncthreads();
    const int j = blockIdx.x * 256 + t;
    float s[NH];
#pragma unroll
    for (int x = 0; x < NH; x++) s[x] = Sm[((long)(b * NH + x)) * 1024 + j];
    for (int n = 0; n < NN; n++) {
        float acc = 0.f;
#pragma unroll
        for (int x = 0; x < NH; x++) acc += As[x * NN + n] * s[x];
        mo[((long)(b * NN + n)) * 1024 + j] = acc;
    }
}

// ---------------- output assembly --------------------------------------------
__device__ __forceinline__ float lis_f(float s) {
    return 8.3f / (1.f + expf(12.f - 10.f * s));
}

__global__ __launch_bounds__(128) void out_kernel(
    const float* __restrict__ enc, const float* __restrict__ Ag,
    const float* __restrict__ coords, const int* __restrict__ labels,
    const float* __restrict__ scores, float* __restrict__ out)
{
    const int b = blockIdx.y, m = blockIdx.x, t = threadIdx.x;
    const int x = m / 63; const int r = m - 63 * x; const int y = r + (r >= x ? 1 : 0);
    const long row = (long)b * MM + m;

    const float4* ex = (const float4*)(enc + ((long)(b * NN + x)) * RR);
    const float4* ey = (const float4*)(enc + ((long)(b * NN + y)) * RR);
    float4* po = (float4*)(out + row * 2048);
#pragma unroll
    for (int i = 0; i < 4; i++) {
        int q = t + (i << 7);
        po[q] = (q < 256) ? ex[q] : ey[q - 256];
    }
    if (t < 4)        out[OFF_BH + row * 4 + t]       = coords[(b * NN + x) * 4 + t];
    else if (t < 8)   out[OFF_BO + row * 4 + (t - 4)] = coords[(b * NN + y) * 4 + (t - 4)];

    const int lbl = labels[b * NN + y];
    const float val = Ag[(b * NH + x) * NN + y] *
                      lis_f(scores[b * NN + x]) * lis_f(scores[b * NN + y]);
    for (int c = t; c < NCLS; c += 128)
        out[OFF_PR + row * (long)NCLS + c] = (c == lbl) ? val : 0.f;
}

// ---------------- host orchestration -----------------------------------------
extern "C" void kernel_launch(void* const* d_in, const int* in_sizes, int n_in,
                              void* d_out, int out_size)
{
    const float* box_features = (const float*)d_in[0];
    const float* box_coords   = (const float*)d_in[1];
    const int*   box_labels   = (const int*)  d_in[2];
    const float* box_scores   = (const float*)d_in[3];
    const float* W1  = (const float*)d_in[4];
    const float* b1  = (const float*)d_in[5];
    const float* W2  = (const float*)d_in[6];
    const float* b2  = (const float*)d_in[7];
    const float* W3  = (const float*)d_in[8];
    const float* b3  = (const float*)d_in[9];
    const float* Ws  = (const float*)d_in[10];
    const float* bs  = (const float*)d_in[11];
    const float* Wo  = (const float*)d_in[12];
    const float* bo  = (const float*)d_in[13];
    const float* Wsu = (const float*)d_in[14];
    const float* Wou = (const float*)d_in[15];
    float* out = (float*)d_out;

    float *encA, *encB, *UV, *O, *mh, *eh, *Sb, *mo, *Ag, *Wuv;
    cudaGetSymbolAddress((void**)&encA, g_encA);
    cudaGetSymbolAddress((void**)&encB, g_encB);
    cudaGetSymbolAddress((void**)&UV,   g_UV);
    cudaGetSymbolAddress((void**)&O,    g_O);
    cudaGetSymbolAddress((void**)&mh,   g_mh);
    cudaGetSymbolAddress((void**)&eh,   g_eh);
    cudaGetSymbolAddress((void**)&Sb,   g_S);
    cudaGetSymbolAddress((void**)&mo,   g_mo);
    cudaGetSymbolAddress((void**)&Ag,   g_A);
    cudaGetSymbolAddress((void**)&Wuv,  g_Wuv);

    cudaFuncSetAttribute(gemm_tf32,
                         cudaFuncAttributeMaxDynamicSharedMemorySize, GEMM_SMEM);
    cudaFuncSetAttribute(pair_mlp_mma,
                         cudaFuncAttributeMaxDynamicSharedMemorySize, PAIR_SMEM);

    // build raw fused Wuv
    fuse_w1<<<512, 256>>>(W1, Wuv);

    cudaMemcpyAsync(encA, box_features, (size_t)BB * NN * RR * 4,
                    cudaMemcpyDeviceToDevice, 0);
    cudaMemsetAsync(Ag, 0, (size_t)BB * NH * NN * 4, 0);

    const long sEnc = (long)NN * RR;   // 65536
    const long sH   = (long)NH * RR;   // 16384

    for (int it = 0; it < 2; it++) {
        float* encIn  = (it == 0) ? encA : encB;
        float* encOut = (it == 0) ? encB : encA;

        // UV = enc @ Wuv  (K=1024, N=2048)
        gemm_tf32<<<dim3(16, 32), 256, GEMM_SMEM>>>(
            encIn, 6, sEnc, 1024, (const float*)0, 0,
            Wuv, (const float*)0, UV, 2048, 2048, 1024, 0);
        // A = sigmoid(pair MLP)
        pair_mlp_mma<<<dim3(16, BB), 512, PAIR_SMEM>>>(
            UV, b1, W2, b2, W3, b3, Ag);
        // O = relu(enc @ Wo + bo)
        gemm_tf32<<<dim3(8, 32), 256, GEMM_SMEM>>>(
            encIn, 6, sEnc, 1024, (const float*)0, 0,
            Wo, bo, O, 1024, 1024, 1024, 1);
        // msg_h = A @ O
        msg_h_k<<<dim3(4, BB), 256>>>(Ag, O, mh);
        // enc_h = concat(enc[:16], msg_h) @ Wsu
        gemm_tf32<<<dim3(8, 8), 256, GEMM_SMEM>>>(
            encIn, 4, sEnc, 1024, mh, sH,
            Wsu, (const float*)0, eh, 1024, 1024, 2048, 0);
        // enc[:16] = enc_h
        cudaMemcpy2DAsync(encIn, (size_t)sEnc * 4, eh, (size_t)sH * 4,
                          (size_t)sH * 4, BB, cudaMemcpyDeviceToDevice, 0);
        // S = relu(enc_h @ Ws + bs)
        gemm_tf32<<<dim3(8, 8), 256, GEMM_SMEM>>>(
            eh, 4, sH, 1024, (const float*)0, 0,
            Ws, bs, Sb, 1024, 1024, 1024, 1);
        // msg_o = A^T @ S
        msg_o_k<<<dim3(4, BB), 256>>>(Ag, Sb, mo);
        // encOut = concat(enc, msg_o) @ Wou
        gemm_tf32<<<dim3(8, 32), 256, GEMM_SMEM>>>(
            encIn, 6, sEnc, 1024, mo, sEnc,
            Wou, (const float*)0, encOut, 1024, 1024, 2048, 0);
    }

    out_kernel<<<dim3(MM, BB), 128>>>(encA, Ag, box_coords, box_labels,
                                      box_scores, out);
    (void)in_sizes; (void)n_in; (void)out_size;
}

// round 6
// speedup vs baseline: 1.6639x; 1.2774x over previous
#include <cuda_runtime.h>
#include <math.h>
#include <stdint.h>

// Problem constants
#define BB   32
#define NN   64
#define NH   16
#define RR   1024
#define REP  1024
#define MM   1008
#define NCLS 117

// Output layout offsets (floats)
#define OFF_BH  66060288L
#define OFF_BO  66189312L
#define OFF_PR  66318336L

// ---------------- scratch (device globals) -----------------------------------
__device__ float g_encA[BB * NN * RR];
__device__ float g_encB[BB * NN * RR];
__device__ float g_UV [BB * NN * 2048];
__device__ float g_O  [BB * NN * REP];
__device__ float g_mh [BB * NH * REP];
__device__ float g_eh [BB * NH * RR];
__device__ float g_S  [BB * NH * REP];
__device__ float g_mo [BB * NN * REP];
__device__ float g_A  [BB * NH * NN];
__device__ float g_Wuv[1024L * 2048];   // fused UV weight (raw): K=1024, N=2048

// ---------------- helpers ----------------------------------------------------
// bf16 m16n8k16 MMA, fp32 accum
__device__ __forceinline__ void mma16(float* c, const uint32_t* a, const uint32_t* b)
{
    asm volatile(
        "mma.sync.aligned.m16n8k16.row.col.f32.bf16.bf16.f32 "
        "{%0,%1,%2,%3}, {%4,%5,%6,%7}, {%8,%9}, {%0,%1,%2,%3};\n"
        : "+f"(c[0]), "+f"(c[1]), "+f"(c[2]), "+f"(c[3])
        : "r"(a[0]), "r"(a[1]), "r"(a[2]), "r"(a[3]), "r"(b[0]), "r"(b[1]));
}

// pack two fp32 into bf16x2 (x0 -> low half = lower k index)
__device__ __forceinline__ uint32_t bpack_hi(float x0, float x1)
{
    uint32_t r;
    asm("cvt.rn.bf16x2.f32 %0, %1, %2;" : "=r"(r) : "f"(x1), "f"(x0));
    return r;
}
// residual (x - hi) packed to bf16x2
__device__ __forceinline__ uint32_t bpack_lo(float x0, float x1, uint32_t hi)
{
    float h0 = __uint_as_float(hi << 16);
    float h1 = __uint_as_float(hi & 0xffff0000u);
    uint32_t r;
    asm("cvt.rn.bf16x2.f32 %0, %1, %2;" : "=r"(r) : "f"(x1 - h1), "f"(x0 - h0));
    return r;
}

__device__ __forceinline__ void cpa16(void* smem, const void* gmem)
{
    uint32_t s = (uint32_t)__cvta_generic_to_shared(smem);
    asm volatile("cp.async.cg.shared.global [%0], [%1], 16;\n" :: "r"(s), "l"(gmem));
}
__device__ __forceinline__ void cp_commit()
{
    asm volatile("cp.async.commit_group;\n");
}
template <int N> __device__ __forceinline__ void cp_wait()
{
    asm volatile("cp.async.wait_group %0;\n" :: "n"(N));
}

// ---------------- build fused Wuv (raw) --------------------------------------
// W1 is [2048, 1024]. Wuv[k][c] = W1[k][c] (c<1024) else W1[1024+k][c-1024].
__global__ __launch_bounds__(256) void fuse_w1(
    const float* __restrict__ W1, float* __restrict__ dst)
{
    for (long i = blockIdx.x * blockDim.x + threadIdx.x; i < 1024L * 2048;
         i += (long)gridDim.x * blockDim.x) {
        int k = (int)(i >> 11), c = (int)(i & 2047);
        dst[i] = (c < 1024) ? W1[(long)k * 1024 + c]
                            : W1[(long)(1024 + k) * 1024 + (c - 1024)];
    }
}

// ---------------- batched GEMM (3xBF16, raw smem, cp.async 2-stage) ----------
// A flat row r -> (b = r>>lrpb, n = r&mask); optional K-concat A2.
// W raw row-major [Ktot, ldw]. C flat [.,ldc]. BM=64, BN=128, BK=32, 256 thr.
#define GEMM_SMEM ((2 * 64 * 36 + 2 * 32 * 136) * 4)
__global__ __launch_bounds__(256, 2) void gemm_bf16x3(
    const float* __restrict__ A1, int lrpb, long sA1, int K1,
    const float* __restrict__ A2, long sA2,
    const float* __restrict__ W, const float* __restrict__ bias,
    float* __restrict__ C, int ldw, int ldc, int Ktot, int do_relu)
{
    extern __shared__ __align__(16) float sm[];
    float* Asr = sm;               // [2][64][36] raw
    float* Bs  = sm + 2 * 2304;    // [2][32][136] raw

    const int t = threadIdx.x, lane = t & 31, warp = t >> 5;
    const int gid = lane >> 2, tig = lane & 3;
    const int wm = warp >> 2, wn = warp & 3;
    const int m0 = wm * 32, n0w = wn * 32;
    const long bn0 = (long)blockIdx.x * 128;
    const int bm0 = blockIdx.y * 64;
    const int K2 = Ktot - K1;
    const int rmask = (1 << lrpb) - 1;

    const int lrow = t >> 3, lk4 = (t & 7) * 4;
    const float* p1[2];
    const float* p2[2];
#pragma unroll
    for (int i = 0; i < 2; i++) {
        int grow = bm0 + lrow + 32 * i;
        int b = grow >> lrpb, n = grow & rmask;
        p1[i] = A1 + (long)b * sA1 + (long)n * K1;
        p2[i] = A2 ? (A2 + (long)b * sA2 + (long)n * K2) : p1[i];
    }

    float c[2][4][4];
#pragma unroll
    for (int mt = 0; mt < 2; mt++)
#pragma unroll
        for (int nt = 0; nt < 4; nt++)
#pragma unroll
            for (int e = 0; e < 4; e++) c[mt][nt][e] = 0.f;

    auto stage = [&](int buf, int k0) {
#pragma unroll
        for (int i = 0; i < 2; i++) {
            const float* src = (k0 < K1) ? (p1[i] + k0 + lk4)
                                         : (p2[i] + (k0 - K1) + lk4);
            cpa16(&Asr[buf * 2304 + (lrow + 32 * i) * 36 + lk4], src);
        }
#pragma unroll
        for (int i = 0; i < 4; i++) {
            int f = t + i * 256;
            int kk = f >> 5, n4 = (f & 31) * 4;
            cpa16(&Bs[buf * 4352 + kk * 136 + n4],
                  W + (long)(k0 + kk) * ldw + bn0 + n4);
        }
        cp_commit();
    };

    stage(0, 0);
    int buf = 0;
    for (int k0 = 0; k0 < Ktot; k0 += 32) {
        const bool more = (k0 + 32 < Ktot);
        if (more) stage(buf ^ 1, k0 + 32);
        if (more) cp_wait<1>(); else cp_wait<0>();
        __syncthreads();

        const float* Ab = &Asr[buf * 2304];
        const float* Bb = &Bs[buf * 4352];
#pragma unroll
        for (int k16 = 0; k16 < 2; k16++) {
            const int kb = k16 * 16;
            uint32_t ah[2][4], al[2][4];
#pragma unroll
            for (int mt = 0; mt < 2; mt++) {
                int r = m0 + mt * 16 + gid;
                float2 a0 = *(const float2*)&Ab[r * 36 + kb + 2 * tig];
                float2 a1 = *(const float2*)&Ab[(r + 8) * 36 + kb + 2 * tig];
                float2 a2 = *(const float2*)&Ab[r * 36 + kb + 2 * tig + 8];
                float2 a3 = *(const float2*)&Ab[(r + 8) * 36 + kb + 2 * tig + 8];
                ah[mt][0] = bpack_hi(a0.x, a0.y); al[mt][0] = bpack_lo(a0.x, a0.y, ah[mt][0]);
                ah[mt][1] = bpack_hi(a1.x, a1.y); al[mt][1] = bpack_lo(a1.x, a1.y, ah[mt][1]);
                ah[mt][2] = bpack_hi(a2.x, a2.y); al[mt][2] = bpack_lo(a2.x, a2.y, ah[mt][2]);
                ah[mt][3] = bpack_hi(a3.x, a3.y); al[mt][3] = bpack_lo(a3.x, a3.y, ah[mt][3]);
            }
#pragma unroll
            for (int nt = 0; nt < 4; nt++) {
                int cn = n0w + nt * 8 + gid;
                float b0 = Bb[(kb + 2 * tig) * 136 + cn];
                float b1 = Bb[(kb + 2 * tig + 1) * 136 + cn];
                float b2 = Bb[(kb + 2 * tig + 8) * 136 + cn];
                float b3 = Bb[(kb + 2 * tig + 9) * 136 + cn];
                uint32_t bh[2], bl[2];
                bh[0] = bpack_hi(b0, b1); bl[0] = bpack_lo(b0, b1, bh[0]);
                bh[1] = bpack_hi(b2, b3); bl[1] = bpack_lo(b2, b3, bh[1]);
#pragma unroll
                for (int mt = 0; mt < 2; mt++) {
                    mma16(c[mt][nt], ah[mt], bh);
                    mma16(c[mt][nt], ah[mt], bl);
                    mma16(c[mt][nt], al[mt], bh);
                }
            }
        }
        __syncthreads();
        buf ^= 1;
    }

#pragma unroll
    for (int mt = 0; mt < 2; mt++) {
#pragma unroll
        for (int nt = 0; nt < 4; nt++) {
            long col = bn0 + n0w + nt * 8 + 2 * tig;
            float b0v = 0.f, b1v = 0.f;
            if (bias) { b0v = bias[col]; b1v = bias[col + 1]; }
            int r = bm0 + m0 + mt * 16 + gid;
            float v0 = c[mt][nt][0] + b0v, v1 = c[mt][nt][1] + b1v;
            float v2 = c[mt][nt][2] + b0v, v3 = c[mt][nt][3] + b1v;
            if (do_relu) {
                v0 = fmaxf(v0, 0.f); v1 = fmaxf(v1, 0.f);
                v2 = fmaxf(v2, 0.f); v3 = fmaxf(v3, 0.f);
            }
            *(float2*)&C[(long)r * ldc + col]       = make_float2(v0, v1);
            *(float2*)&C[(long)(r + 8) * ldc + col] = make_float2(v2, v3);
        }
    }
}

// ---------------- fused pair MLP (3xBF16, raw W2, cp.async 2-stage) ----------
// BM=64 pairs, BN=512 (full width), BK=32, 512 threads. grid (16, 32).
#define PAIR_SMEM ((2 * 64 * 36 + 2 * 32 * 520 + 64 * 8) * 4)
__global__ __launch_bounds__(512, 1) void pair_mlp_mma(
    const float* __restrict__ UV, const float* __restrict__ b1,
    const float* __restrict__ W2, const float* __restrict__ b2,
    const float* __restrict__ W3, const float* __restrict__ b3,
    float* __restrict__ Aout)
{
    extern __shared__ __align__(16) float sm[];
    float* h1s   = sm;                       // [2][64][36] raw
    float* Bs    = sm + 2 * 2304;            // [2][32][520] raw
    float* wpart = sm + 2 * 2304 + 2 * 16640; // [64][8]

    const int t = threadIdx.x, lane = t & 31, warp = t >> 5;
    const int gid = lane >> 2, tig = lane & 3;
    const int wm = warp >> 3, wn = warp & 7;
    const int m0 = wm * 32, n0w = wn * 64;
    const int bi = blockIdx.y;

    // h1 loader role: one float4 of k per thread per stage
    const int lr = t >> 3, k4 = (t & 7) * 4;
    const int mld = blockIdx.x * 64 + lr;
    const int valid = (mld < MM);
    int xl = 0, yl = 0;
    if (valid) { xl = mld / 63; int rl = mld - 63 * xl; yl = rl + (rl >= xl ? 1 : 0); }
    const float* Urow = UV + ((long)(bi * 64 + xl)) * 2048;
    const float* Vrow = UV + ((long)(bi * 64 + yl)) * 2048 + 1024;

    float c[2][8][4];
#pragma unroll
    for (int mt = 0; mt < 2; mt++)
#pragma unroll
        for (int nt = 0; nt < 8; nt++)
#pragma unroll
            for (int e = 0; e < 4; e++) c[mt][nt][e] = 0.f;

    auto stage = [&](int buf, int k0) {
        // h1 tile
        float4 u  = *(const float4*)(Urow + k0 + k4);
        float4 v  = *(const float4*)(Vrow + k0 + k4);
        float4 bb = *(const float4*)(b1 + k0 + k4);
        float4 h;
        h.x = fmaxf(u.x + v.x + bb.x, 0.f);
        h.y = fmaxf(u.y + v.y + bb.y, 0.f);
        h.z = fmaxf(u.z + v.z + bb.z, 0.f);
        h.w = fmaxf(u.w + v.w + bb.w, 0.f);
        if (!valid) h = make_float4(0.f, 0.f, 0.f, 0.f);
        *(float4*)&h1s[buf * 2304 + lr * 36 + k4] = h;
        // W2 slab [32][512] raw via cp.async
#pragma unroll
        for (int i = 0; i < 8; i++) {
            int f = t + i * 512;
            int kk = f >> 7, n4 = (f & 127) * 4;
            cpa16(&Bs[buf * 16640 + kk * 520 + n4],
                  W2 + (long)(k0 + kk) * 512 + n4);
        }
        cp_commit();
    };

    stage(0, 0);
    int buf = 0;
    for (int k0 = 0; k0 < REP; k0 += 32) {
        const bool more = (k0 + 32 < REP);
        if (more) stage(buf ^ 1, k0 + 32);
        if (more) cp_wait<1>(); else cp_wait<0>();
        __syncthreads();

        const float* Ab = &h1s[buf * 2304];
        const float* Bb = &Bs[buf * 16640];
#pragma unroll
        for (int k16 = 0; k16 < 2; k16++) {
            const int kb = k16 * 16;
            uint32_t ah[2][4], al[2][4];
#pragma unroll
            for (int mt = 0; mt < 2; mt++) {
                int r = m0 + mt * 16 + gid;
                float2 a0 = *(const float2*)&Ab[r * 36 + kb + 2 * tig];
                float2 a1 = *(const float2*)&Ab[(r + 8) * 36 + kb + 2 * tig];
                float2 a2 = *(const float2*)&Ab[r * 36 + kb + 2 * tig + 8];
                float2 a3 = *(const float2*)&Ab[(r + 8) * 36 + kb + 2 * tig + 8];
                ah[mt][0] = bpack_hi(a0.x, a0.y); al[mt][0] = bpack_lo(a0.x, a0.y, ah[mt][0]);
                ah[mt][1] = bpack_hi(a1.x, a1.y); al[mt][1] = bpack_lo(a1.x, a1.y, ah[mt][1]);
                ah[mt][2] = bpack_hi(a2.x, a2.y); al[mt][2] = bpack_lo(a2.x, a2.y, ah[mt][2]);
                ah[mt][3] = bpack_hi(a3.x, a3.y); al[mt][3] = bpack_lo(a3.x, a3.y, ah[mt][3]);
            }
#pragma unroll
            for (int nt = 0; nt < 8; nt++) {
                int cn = n0w + nt * 8 + gid;
                float b0 = Bb[(kb + 2 * tig) * 520 + cn];
                float b1 = Bb[(kb + 2 * tig + 1) * 520 + cn];
                float b2 = Bb[(kb + 2 * tig + 8) * 520 + cn];
                float b3 = Bb[(kb + 2 * tig + 9) * 520 + cn];
                uint32_t bh[2], bl[2];
                bh[0] = bpack_hi(b0, b1); bl[0] = bpack_lo(b0, b1, bh[0]);
                bh[1] = bpack_hi(b2, b3); bl[1] = bpack_lo(b2, b3, bh[1]);
#pragma unroll
                for (int mt = 0; mt < 2; mt++) {
                    mma16(c[mt][nt], ah[mt], bh);
                    mma16(c[mt][nt], ah[mt], bl);
                    mma16(c[mt][nt], al[mt], bh);
                }
            }
        }
        __syncthreads();
        buf ^= 1;
    }

    // epilogue: h2 = relu(c + b2); partial w = h2 @ W3
    float rp[4] = { 0.f, 0.f, 0.f, 0.f };
#pragma unroll
    for (int mt = 0; mt < 2; mt++) {
#pragma unroll
        for (int nt = 0; nt < 8; nt++) {
            int col = n0w + nt * 8 + 2 * tig;
            float b2a = b2[col], b2b = b2[col + 1];
            float w3a = W3[col], w3b = W3[col + 1];
            rp[2 * mt + 0] += fmaxf(c[mt][nt][0] + b2a, 0.f) * w3a
                            + fmaxf(c[mt][nt][1] + b2b, 0.f) * w3b;
            rp[2 * mt + 1] += fmaxf(c[mt][nt][2] + b2a, 0.f) * w3a
                            + fmaxf(c[mt][nt][3] + b2b, 0.f) * w3b;
        }
    }
#pragma unroll
    for (int e = 0; e < 4; e++) {
        float v = rp[e];
        v += __shfl_xor_sync(0xffffffffu, v, 1);
        v += __shfl_xor_sync(0xffffffffu, v, 2);
        int mt = e >> 1, o = e & 1;
        if (tig == 0) wpart[(m0 + mt * 16 + o * 8 + gid) * 8 + wn] = v;
    }
    __syncthreads();
    if (t < 64) {
        float s = b3[0];
#pragma unroll
        for (int w = 0; w < 8; w++) s += wpart[t * 8 + w];
        int m = blockIdx.x * 64 + t;
        if (m < MM) {
            int x = m / 63; int r = m - 63 * x; int y = r + (r >= x ? 1 : 0);
            Aout[(bi * 16 + x) * 64 + y] = 1.f / (1.f + expf(-s));
        }
    }
}

// ---------------- msg_h = A @ O ----------------------------------------------
__global__ __launch_bounds__(256) void msg_h_k(
    const float* __restrict__ Ag, const float* __restrict__ O, float* __restrict__ mh)
{
    __shared__ float As[NH * NN];
    const int b = blockIdx.y, t = threadIdx.x;
#pragma unroll
    for (int i = 0; i < 4; i++) As[t + 256 * i] = Ag[b * NH * NN + t + 256 * i];
    __syncthreads();
    const int j = blockIdx.x * 256 + t;
    float acc[NH];
#pragma unroll
    for (int x = 0; x < NH; x++) acc[x] = 0.f;
    for (int n = 0; n < NN; n++) {
        float o = O[((long)(b * NN + n)) * 1024 + j];
#pragma unroll
        for (int x = 0; x < NH; x++) acc[x] += As[x * NN + n] * o;
    }
#pragma unroll
    for (int x = 0; x < NH; x++) mh[((long)(b * NH + x)) * 1024 + j] = acc[x];
}

// ---------------- msg_o = A^T @ S --------------------------------------------
__global__ __launch_bounds__(256) void msg_o_k(
    const float* __restrict__ Ag, const float* __restrict__ Sm, float* __restrict__ mo)
{
    __shared__ float As[NH * NN];
    const int b = blockIdx.y, t = threadIdx.x;
#pragma unroll
    for (int i = 0; i < 4; i++) As[t + 256 * i] = Ag[b * NH * NN + t + 256 * i];
    __syncthreads();
    const int j = blockIdx.x * 256 + t;
    float s[NH];
#pragma unroll
    for (int x = 0; x < NH; x++) s[x] = Sm[((long)(b * NH + x)) * 1024 + j];
    for (int n = 0; n < NN; n++) {
        float acc = 0.f;
#pragma unroll
        for (int x = 0; x < NH; x++) acc += As[x * NN + n] * s[x];
        mo[((long)(b * NN + n)) * 1024 + j] = acc;
    }
}

// ---------------- output assembly --------------------------------------------
__device__ __forceinline__ float lis_f(float s) {
    return 8.3f / (1.f + expf(12.f - 10.f * s));
}

__global__ __launch_bounds__(128) void out_kernel(
    const float* __restrict__ enc, const float* __restrict__ Ag,
    const float* __restrict__ coords, const int* __restrict__ labels,
    const float* __restrict__ scores, float* __restrict__ out)
{
    const int b = blockIdx.y, m = blockIdx.x, t = threadIdx.x;
    const int x = m / 63; const int r = m - 63 * x; const int y = r + (r >= x ? 1 : 0);
    const long row = (long)b * MM + m;

    const float4* ex = (const float4*)(enc + ((long)(b * NN + x)) * RR);
    const float4* ey = (const float4*)(enc + ((long)(b * NN + y)) * RR);
    float4* po = (float4*)(out + row * 2048);
#pragma unroll
    for (int i = 0; i < 4; i++) {
        int q = t + (i << 7);
        po[q] = (q < 256) ? ex[q] : ey[q - 256];
    }
    if (t < 4)        out[OFF_BH + row * 4 + t]       = coords[(b * NN + x) * 4 + t];
    else if (t < 8)   out[OFF_BO + row * 4 + (t - 4)] = coords[(b * NN + y) * 4 + (t - 4)];

    const int lbl = labels[b * NN + y];
    const float val = Ag[(b * NH + x) * NN + y] *
                      lis_f(scores[b * NN + x]) * lis_f(scores[b * NN + y]);
    for (int c = t; c < NCLS; c += 128)
        out[OFF_PR + row * (long)NCLS + c] = (c == lbl) ? val : 0.f;
}

// ---------------- host orchestration -----------------------------------------
extern "C" void kernel_launch(void* const* d_in, const int* in_sizes, int n_in,
                              void* d_out, int out_size)
{
    const float* box_features = (const float*)d_in[0];
    const float* box_coords   = (const float*)d_in[1];
    const int*   box_labels   = (const int*)  d_in[2];
    const float* box_scores   = (const float*)d_in[3];
    const float* W1  = (const float*)d_in[4];
    const float* b1  = (const float*)d_in[5];
    const float* W2  = (const float*)d_in[6];
    const float* b2  = (const float*)d_in[7];
    const float* W3  = (const float*)d_in[8];
    const float* b3  = (const float*)d_in[9];
    const float* Ws  = (const float*)d_in[10];
    const float* bs  = (const float*)d_in[11];
    const float* Wo  = (const float*)d_in[12];
    const float* bo  = (const float*)d_in[13];
    const float* Wsu = (const float*)d_in[14];
    const float* Wou = (const float*)d_in[15];
    float* out = (float*)d_out;

    float *encA, *encB, *UV, *O, *mh, *eh, *Sb, *mo, *Ag, *Wuv;
    cudaGetSymbolAddress((void**)&encA, g_encA);
    cudaGetSymbolAddress((void**)&encB, g_encB);
    cudaGetSymbolAddress((void**)&UV,   g_UV);
    cudaGetSymbolAddress((void**)&O,    g_O);
    cudaGetSymbolAddress((void**)&mh,   g_mh);
    cudaGetSymbolAddress((void**)&eh,   g_eh);
    cudaGetSymbolAddress((void**)&Sb,   g_S);
    cudaGetSymbolAddress((void**)&mo,   g_mo);
    cudaGetSymbolAddress((void**)&Ag,   g_A);
    cudaGetSymbolAddress((void**)&Wuv,  g_Wuv);

    cudaFuncSetAttribute(gemm_bf16x3,
                         cudaFuncAttributeMaxDynamicSharedMemorySize, GEMM_SMEM);
    cudaFuncSetAttribute(pair_mlp_mma,
                         cudaFuncAttributeMaxDynamicSharedMemorySize, PAIR_SMEM);

    // build raw fused Wuv
    fuse_w1<<<512, 256>>>(W1, Wuv);

    cudaMemcpyAsync(encA, box_features, (size_t)BB * NN * RR * 4,
                    cudaMemcpyDeviceToDevice, 0);

    const long sEnc = (long)NN * RR;   // 65536
    const long sH   = (long)NH * RR;   // 16384

    for (int it = 0; it < 2; it++) {
        float* encIn  = (it == 0) ? encA : encB;
        float* encOut = (it == 0) ? encB : encA;

        // UV = enc @ Wuv  (K=1024, N=2048)
        gemm_bf16x3<<<dim3(16, 32), 256, GEMM_SMEM>>>(
            encIn, 6, sEnc, 1024, (const float*)0, 0,
            Wuv, (const float*)0, UV, 2048, 2048, 1024, 0);
        // A = sigmoid(pair MLP)
        pair_mlp_mma<<<dim3(16, BB), 512, PAIR_SMEM>>>(
            UV, b1, W2, b2, W3, b3, Ag);
        // O = relu(enc @ Wo + bo)
        gemm_bf16x3<<<dim3(8, 32), 256, GEMM_SMEM>>>(
            encIn, 6, sEnc, 1024, (const float*)0, 0,
            Wo, bo, O, 1024, 1024, 1024, 1);
        // msg_h = A @ O
        msg_h_k<<<dim3(4, BB), 256>>>(Ag, O, mh);
        // enc_h = concat(enc[:16], msg_h) @ Wsu
        gemm_bf16x3<<<dim3(8, 8), 256, GEMM_SMEM>>>(
            encIn, 4, sEnc, 1024, mh, sH,
            Wsu, (const float*)0, eh, 1024, 1024, 2048, 0);
        // enc[:16] = enc_h
        cudaMemcpy2DAsync(encIn, (size_t)sEnc * 4, eh, (size_t)sH * 4,
                          (size_t)sH * 4, BB, cudaMemcpyDeviceToDevice, 0);
        // S = relu(enc_h @ Ws + bs)
        gemm_bf16x3<<<dim3(8, 8), 256, GEMM_SMEM>>>(
            eh, 4, sH, 1024, (const float*)0, 0,
            Ws, bs, Sb, 1024, 1024, 1024, 1);
        // msg_o = A^T @ S
        msg_o_k<<<dim3(4, BB), 256>>>(Ag, Sb, mo);
        // encOut = concat(enc, msg_o) @ Wou
        gemm_bf16x3<<<dim3(8, 32), 256, GEMM_SMEM>>>(
            encIn, 6, sEnc, 1024, mo, sEnc,
            Wou, (const float*)0, encOut, 1024, 1024, 2048, 0);
    }

    out_kernel<<<dim3(MM, BB), 128>>>(encA, Ag, box_coords, box_labels,
                                      box_scores, out);
    (void)in_sizes; (void)n_in; (void)out_size;
}

// round 7
// speedup vs baseline: 2.0632x; 1.2400x over previous
#include <cuda_runtime.h>
#include <math.h>
#include <stdint.h>

// Problem constants
#define BB   32
#define NN   64
#define NH   16
#define RR   1024
#define REP  1024
#define MM   1008
#define NCLS 117

// Output layout offsets (floats)
#define OFF_BH  66060288L
#define OFF_BO  66189312L
#define OFF_PR  66318336L

// ---------------- scratch (device globals) -----------------------------------
__device__ float g_encA[BB * NN * RR];
__device__ float g_encB[BB * NN * RR];
__device__ float g_UV [BB * NN * 2048];
__device__ float g_O  [BB * NN * REP];
__device__ float g_mh [BB * NH * REP];
__device__ float g_eh [BB * NH * RR];
__device__ float g_S  [BB * NH * REP];
__device__ float g_mo [BB * NN * REP];
__device__ float g_A  [BB * NH * NN];

// packed weights: hi plane then lo plane, each [K/2][N] uint32 k-pair words
__device__ uint32_t g_W1p [1024L * 2048];  // fused UV: K=1024, N=2048
__device__ uint32_t g_W2p [1024L * 512];   // K=1024, N=512
__device__ uint32_t g_Wop [1024L * 1024];
__device__ uint32_t g_Wsp [1024L * 1024];
__device__ uint32_t g_Wsup[2048L * 1024];  // K=2048
__device__ uint32_t g_Woup[2048L * 1024];  // K=2048

// ---------------- helpers ----------------------------------------------------
__device__ __forceinline__ void mma16(float* c, const uint32_t* a, const uint32_t* b)
{
    asm volatile(
        "mma.sync.aligned.m16n8k16.row.col.f32.bf16.bf16.f32 "
        "{%0,%1,%2,%3}, {%4,%5,%6,%7}, {%8,%9}, {%0,%1,%2,%3};\n"
        : "+f"(c[0]), "+f"(c[1]), "+f"(c[2]), "+f"(c[3])
        : "r"(a[0]), "r"(a[1]), "r"(a[2]), "r"(a[3]), "r"(b[0]), "r"(b[1]));
}

// pack two fp32 into bf16x2 (x0 -> low half = lower k index)
__device__ __forceinline__ uint32_t pk_hi(float x0, float x1)
{
    uint32_t r;
    asm("cvt.rn.bf16x2.f32 %0, %1, %2;" : "=r"(r) : "f"(x1), "f"(x0));
    return r;
}
__device__ __forceinline__ uint32_t pk_lo(float x0, float x1, uint32_t hi)
{
    float h0 = __uint_as_float(hi << 16);
    float h1 = __uint_as_float(hi & 0xffff0000u);
    uint32_t r;
    asm("cvt.rn.bf16x2.f32 %0, %1, %2;" : "=r"(r) : "f"(x1 - h1), "f"(x0 - h0));
    return r;
}

__device__ __forceinline__ void cpa16(void* smem, const void* gmem)
{
    uint32_t s = (uint32_t)__cvta_generic_to_shared(smem);
    asm volatile("cp.async.cg.shared.global [%0], [%1], 16;\n" :: "r"(s), "l"(gmem));
}
__device__ __forceinline__ void cp_commit()
{
    asm volatile("cp.async.commit_group;\n");
}
template <int N> __device__ __forceinline__ void cp_wait()
{
    asm volatile("cp.async.wait_group %0;\n" :: "n"(N));
}

// ---------------- weight prepack ---------------------------------------------
// W [K,N] fp32 -> Wp: hi plane [K/2][N] words then lo plane. word = (bf16(W[2kp][n]), bf16(W[2kp+1][n]))
__global__ __launch_bounds__(256) void pack_w(
    const float* __restrict__ W, uint32_t* __restrict__ Wp, int Kh, int N)
{
    long total = (long)Kh * N;
    for (long i = blockIdx.x * blockDim.x + threadIdx.x; i < total;
         i += (long)gridDim.x * blockDim.x) {
        int kp = (int)(i / N), n = (int)(i - (long)kp * N);
        float x0 = W[(long)(2 * kp) * N + n];
        float x1 = W[(long)(2 * kp + 1) * N + n];
        uint32_t hi = pk_hi(x0, x1);
        Wp[i] = hi;
        Wp[total + i] = pk_lo(x0, x1, hi);
    }
}

// fused UV pack. W1 [2048,1024]: F(k,c) = c<1024 ? W1[k][c] : W1[1024+k][c-1024]
__global__ __launch_bounds__(256) void pack_wuv(
    const float* __restrict__ W1, uint32_t* __restrict__ Wp)
{
    const long total = 512L * 2048;
    for (long i = blockIdx.x * blockDim.x + threadIdx.x; i < total;
         i += (long)gridDim.x * blockDim.x) {
        int kp = (int)(i >> 11), c = (int)(i & 2047);
        float x0, x1;
        if (c < 1024) {
            x0 = W1[(long)(2 * kp) * 1024 + c];
            x1 = W1[(long)(2 * kp + 1) * 1024 + c];
        } else {
            x0 = W1[(long)(1024 + 2 * kp) * 1024 + (c - 1024)];
            x1 = W1[(long)(1024 + 2 * kp + 1) * 1024 + (c - 1024)];
        }
        uint32_t hi = pk_hi(x0, x1);
        Wp[i] = hi;
        Wp[total + i] = pk_lo(x0, x1, hi);
    }
}

// ---------------- batched GEMM (3xBF16, packed W planes) ---------------------
// BM=64, BN=128, BK=32 (16 k-pairs), 256 threads.
// smem: A [2 buf][2 plane][64][20] = 5120 w; B [2][2][16][136] = 8704 w.
#define GEMM_SMEM ((5120 + 8704) * 4)
__global__ __launch_bounds__(256, 2) void gemm_bf16p(
    const float* __restrict__ A1, int lrpb, long sA1, int K1,
    const float* __restrict__ A2, long sA2,
    const uint32_t* __restrict__ Wp, const float* __restrict__ bias,
    float* __restrict__ C, int Nw, long PKw, int ldc, int Ktot, int do_relu)
{
    extern __shared__ __align__(16) uint32_t sm[];
    uint32_t* As = sm;          // A planes
    uint32_t* Bs = sm + 5120;   // B planes

    const int t = threadIdx.x, lane = t & 31, warp = t >> 5;
    const int gid = lane >> 2, tig = lane & 3;
    const int wm = warp >> 2, wn = warp & 3;
    const int m0 = wm * 32, n0w = wn * 32;
    const long bn0 = (long)blockIdx.x * 128;
    const int bm0 = blockIdx.y * 64;
    const int K2 = Ktot - K1;
    const int rmask = (1 << lrpb) - 1;

    // A loader: one row per thread, two float4 at k = lf4*4 and +16
    const int lrow = t >> 2, lf4 = t & 3;
    {
    }
    const int grow = bm0 + lrow;
    const int b = grow >> lrpb, n = grow & rmask;
    const float* p1 = A1 + (long)b * sA1 + (long)n * K1;
    const float* p2 = A2 ? (A2 + (long)b * sA2 + (long)n * K2) : p1;

    float4 ra0, ra1;
    auto ldgA = [&](int k0) {
        const float* rp = (k0 < K1) ? (p1 + k0) : (p2 + (k0 - K1));
        ra0 = *(const float4*)(rp + lf4 * 4);
        ra1 = *(const float4*)(rp + lf4 * 4 + 16);
    };
    auto stsA = [&](int buf) {
        uint32_t* Ah = As + buf * 2560 + lrow * 20;
        uint32_t* Al = Ah + 1280;
        const int w = lf4 * 2;
        uint32_t h0 = pk_hi(ra0.x, ra0.y), h1 = pk_hi(ra0.z, ra0.w);
        uint32_t h2 = pk_hi(ra1.x, ra1.y), h3 = pk_hi(ra1.z, ra1.w);
        Ah[w] = h0; Ah[w + 1] = h1; Ah[w + 8] = h2; Ah[w + 9] = h3;
        Al[w]     = pk_lo(ra0.x, ra0.y, h0);
        Al[w + 1] = pk_lo(ra0.z, ra0.w, h1);
        Al[w + 8] = pk_lo(ra1.x, ra1.y, h2);
        Al[w + 9] = pk_lo(ra1.z, ra1.w, h3);
    };
    auto stageB = [&](int buf, int k0) {
        const long kp0 = k0 >> 1;
#pragma unroll
        for (int i = 0; i < 4; i++) {
            int f = t + i * 256;
            int plane = f >> 9, g = f & 511;
            int kk = g >> 5, n4 = (g & 31) * 4;
            cpa16(&Bs[buf * 4352 + plane * 2176 + kk * 136 + n4],
                  Wp + plane * PKw + (kp0 + kk) * Nw + bn0 + n4);
        }
        cp_commit();
    };

    float c[2][4][4];
#pragma unroll
    for (int mt = 0; mt < 2; mt++)
#pragma unroll
        for (int nt = 0; nt < 4; nt++)
#pragma unroll
            for (int e = 0; e < 4; e++) c[mt][nt][e] = 0.f;

    ldgA(0); stageB(0, 0); stsA(0);
    int buf = 0;
    for (int k0 = 0; k0 < Ktot; k0 += 32) {
        const bool more = (k0 + 32 < Ktot);
        cp_wait<0>();
        __syncthreads();
        if (more) { ldgA(k0 + 32); stageB(buf ^ 1, k0 + 32); }

        const uint32_t* Ah = As + buf * 2560;
        const uint32_t* Al = Ah + 1280;
        const uint32_t* Bh = Bs + buf * 4352;
        const uint32_t* Bl = Bh + 2176;
#pragma unroll
        for (int k16 = 0; k16 < 2; k16++) {
            const int kb = k16 * 8;
            uint32_t ah[2][4], al[2][4];
#pragma unroll
            for (int mt = 0; mt < 2; mt++) {
                int r0 = (m0 + mt * 16 + gid) * 20;
                int r1 = r0 + 160;
                ah[mt][0] = Ah[r0 + kb + tig];
                ah[mt][1] = Ah[r1 + kb + tig];
                ah[mt][2] = Ah[r0 + kb + tig + 4];
                ah[mt][3] = Ah[r1 + kb + tig + 4];
                al[mt][0] = Al[r0 + kb + tig];
                al[mt][1] = Al[r1 + kb + tig];
                al[mt][2] = Al[r0 + kb + tig + 4];
                al[mt][3] = Al[r1 + kb + tig + 4];
            }
#pragma unroll
            for (int nt = 0; nt < 4; nt++) {
                int cn = n0w + nt * 8 + gid;
                uint32_t bh[2], bl[2];
                bh[0] = Bh[(kb + tig) * 136 + cn];
                bh[1] = Bh[(kb + tig + 4) * 136 + cn];
                bl[0] = Bl[(kb + tig) * 136 + cn];
                bl[1] = Bl[(kb + tig + 4) * 136 + cn];
#pragma unroll
                for (int mt = 0; mt < 2; mt++) {
                    mma16(c[mt][nt], ah[mt], bh);
                    mma16(c[mt][nt], ah[mt], bl);
                    mma16(c[mt][nt], al[mt], bh);
                }
            }
        }
        if (more) stsA(buf ^ 1);
        buf ^= 1;
    }

#pragma unroll
    for (int mt = 0; mt < 2; mt++) {
#pragma unroll
        for (int nt = 0; nt < 4; nt++) {
            long col = bn0 + n0w + nt * 8 + 2 * tig;
            float b0v = 0.f, b1v = 0.f;
            if (bias) { b0v = bias[col]; b1v = bias[col + 1]; }
            int r = bm0 + m0 + mt * 16 + gid;
            float v0 = c[mt][nt][0] + b0v, v1 = c[mt][nt][1] + b1v;
            float v2 = c[mt][nt][2] + b0v, v3 = c[mt][nt][3] + b1v;
            if (do_relu) {
                v0 = fmaxf(v0, 0.f); v1 = fmaxf(v1, 0.f);
                v2 = fmaxf(v2, 0.f); v3 = fmaxf(v3, 0.f);
            }
            *(float2*)&C[(long)r * ldc + col]       = make_float2(v0, v1);
            *(float2*)&C[(long)(r + 8) * ldc + col] = make_float2(v2, v3);
        }
    }
}

// ---------------- fused pair MLP (3xBF16, packed W2 planes) ------------------
// BM=64 pairs, BN=512, BK=32 (16 k-pairs), 512 threads. grid (16, 32).
// smem: A 5120 w; B [2][2][16][520] = 33280 w; wpart 512 w.
#define PAIR_SMEM ((5120 + 33280 + 512) * 4)
__global__ __launch_bounds__(512, 1) void pair_mlp_mma(
    const float* __restrict__ UV, const float* __restrict__ b1,
    const uint32_t* __restrict__ W2p, const float* __restrict__ b2,
    const float* __restrict__ W3, const float* __restrict__ b3,
    float* __restrict__ Aout)
{
    extern __shared__ __align__(16) uint32_t sm[];
    uint32_t* As = sm;
    uint32_t* Bs = sm + 5120;
    float* wpart = (float*)(sm + 5120 + 33280);

    const int t = threadIdx.x, lane = t & 31, warp = t >> 5;
    const int gid = lane >> 2, tig = lane & 3;
    const int wm = warp >> 3, wn = warp & 7;
    const int m0 = wm * 32, n0w = wn * 64;
    const int bi = blockIdx.y;
    const long PK2 = 512L * 512;

    // h1 loader: one float4 of k per thread
    const int lr = t >> 3, k4 = (t & 7) * 4;
    const int mld = blockIdx.x * 64 + lr;
    const int valid = (mld < MM);
    int xl = 0, yl = 0;
    if (valid) { xl = mld / 63; int rl = mld - 63 * xl; yl = rl + (rl >= xl ? 1 : 0); }
    const float* Urow = UV + ((long)(bi * 64 + xl)) * 2048;
    const float* Vrow = UV + ((long)(bi * 64 + yl)) * 2048 + 1024;

    float4 ru, rv, rb;
    auto ldgA = [&](int k0) {
        ru = *(const float4*)(Urow + k0 + k4);
        rv = *(const float4*)(Vrow + k0 + k4);
        rb = *(const float4*)(b1 + k0 + k4);
    };
    auto stsA = [&](int buf) {
        float4 h;
        h.x = fmaxf(ru.x + rv.x + rb.x, 0.f);
        h.y = fmaxf(ru.y + rv.y + rb.y, 0.f);
        h.z = fmaxf(ru.z + rv.z + rb.z, 0.f);
        h.w = fmaxf(ru.w + rv.w + rb.w, 0.f);
        if (!valid) h = make_float4(0.f, 0.f, 0.f, 0.f);
        uint32_t* Ah = As + buf * 2560 + lr * 20;
        uint32_t* Al = Ah + 1280;
        const int w = (t & 7) * 2;
        uint32_t h0 = pk_hi(h.x, h.y), h1 = pk_hi(h.z, h.w);
        Ah[w] = h0; Ah[w + 1] = h1;
        Al[w]     = pk_lo(h.x, h.y, h0);
        Al[w + 1] = pk_lo(h.z, h.w, h1);
    };
    auto stageB = [&](int buf, int k0) {
        const long kp0 = k0 >> 1;
#pragma unroll
        for (int i = 0; i < 8; i++) {
            int f = t + i * 512;
            int plane = f >> 11, g = f & 2047;
            int kk = g >> 7, n4 = (g & 127) * 4;
            cpa16(&Bs[buf * 16640 + plane * 8320 + kk * 520 + n4],
                  W2p + plane * PK2 + (kp0 + kk) * 512 + n4);
        }
        cp_commit();
    };

    float c[2][8][4];
#pragma unroll
    for (int mt = 0; mt < 2; mt++)
#pragma unroll
        for (int nt = 0; nt < 8; nt++)
#pragma unroll
            for (int e = 0; e < 4; e++) c[mt][nt][e] = 0.f;

    ldgA(0); stageB(0, 0); stsA(0);
    int buf = 0;
    for (int k0 = 0; k0 < REP; k0 += 32) {
        const bool more = (k0 + 32 < REP);
        cp_wait<0>();
        __syncthreads();
        if (more) { ldgA(k0 + 32); stageB(buf ^ 1, k0 + 32); }

        const uint32_t* Ah = As + buf * 2560;
        const uint32_t* Al = Ah + 1280;
        const uint32_t* Bh = Bs + buf * 16640;
        const uint32_t* Bl = Bh + 8320;
#pragma unroll
        for (int k16 = 0; k16 < 2; k16++) {
            const int kb = k16 * 8;
            uint32_t ah[2][4], al[2][4];
#pragma unroll
            for (int mt = 0; mt < 2; mt++) {
                int r0 = (m0 + mt * 16 + gid) * 20;
                int r1 = r0 + 160;
                ah[mt][0] = Ah[r0 + kb + tig];
                ah[mt][1] = Ah[r1 + kb + tig];
                ah[mt][2] = Ah[r0 + kb + tig + 4];
                ah[mt][3] = Ah[r1 + kb + tig + 4];
                al[mt][0] = Al[r0 + kb + tig];
                al[mt][1] = Al[r1 + kb + tig];
                al[mt][2] = Al[r0 + kb + tig + 4];
                al[mt][3] = Al[r1 + kb + tig + 4];
            }
#pragma unroll
            for (int nt = 0; nt < 8; nt++) {
                int cn = n0w + nt * 8 + gid;
                uint32_t bh[2], bl[2];
                bh[0] = Bh[(kb + tig) * 520 + cn];
                bh[1] = Bh[(kb + tig + 4) * 520 + cn];
                bl[0] = Bl[(kb + tig) * 520 + cn];
                bl[1] = Bl[(kb + tig + 4) * 520 + cn];
#pragma unroll
                for (int mt = 0; mt < 2; mt++) {
                    mma16(c[mt][nt], ah[mt], bh);
                    mma16(c[mt][nt], ah[mt], bl);
                    mma16(c[mt][nt], al[mt], bh);
                }
            }
        }
        if (more) stsA(buf ^ 1);
        buf ^= 1;
    }

    // epilogue: h2 = relu(c + b2); partial w = h2 @ W3
    float rp[4] = { 0.f, 0.f, 0.f, 0.f };
#pragma unroll
    for (int mt = 0; mt < 2; mt++) {
#pragma unroll
        for (int nt = 0; nt < 8; nt++) {
            int col = n0w + nt * 8 + 2 * tig;
            float b2a = b2[col], b2b = b2[col + 1];
            float w3a = W3[col], w3b = W3[col + 1];
            rp[2 * mt + 0] += fmaxf(c[mt][nt][0] + b2a, 0.f) * w3a
                            + fmaxf(c[mt][nt][1] + b2b, 0.f) * w3b;
            rp[2 * mt + 1] += fmaxf(c[mt][nt][2] + b2a, 0.f) * w3a
                            + fmaxf(c[mt][nt][3] + b2b, 0.f) * w3b;
        }
    }
#pragma unroll
    for (int e = 0; e < 4; e++) {
        float v = rp[e];
        v += __shfl_xor_sync(0xffffffffu, v, 1);
        v += __shfl_xor_sync(0xffffffffu, v, 2);
        int mt = e >> 1, o = e & 1;
        if (tig == 0) wpart[(m0 + mt * 16 + o * 8 + gid) * 8 + wn] = v;
    }
    __syncthreads();
    if (t < 64) {
        float s = b3[0];
#pragma unroll
        for (int w = 0; w < 8; w++) s += wpart[t * 8 + w];
        int m = blockIdx.x * 64 + t;
        if (m < MM) {
            int x = m / 63; int r = m - 63 * x; int y = r + (r >= x ? 1 : 0);
            Aout[(bi * 16 + x) * 64 + y] = 1.f / (1.f + expf(-s));
        }
    }
}

// ---------------- msg_h = A @ O ----------------------------------------------
__global__ __launch_bounds__(256) void msg_h_k(
    const float* __restrict__ Ag, const float* __restrict__ O, float* __restrict__ mh)
{
    __shared__ float As[NH * NN];
    const int b = blockIdx.y, t = threadIdx.x;
#pragma unroll
    for (int i = 0; i < 4; i++) As[t + 256 * i] = Ag[b * NH * NN + t + 256 * i];
    __syncthreads();
    const int j = blockIdx.x * 256 + t;
    float acc[NH];
#pragma unroll
    for (int x = 0; x < NH; x++) acc[x] = 0.f;
    for (int n = 0; n < NN; n++) {
        float o = O[((long)(b * NN + n)) * 1024 + j];
#pragma unroll
        for (int x = 0; x < NH; x++) acc[x] += As[x * NN + n] * o;
    }
#pragma unroll
    for (int x = 0; x < NH; x++) mh[((long)(b * NH + x)) * 1024 + j] = acc[x];
}

// ---------------- msg_o = A^T @ S --------------------------------------------
__global__ __launch_bounds__(256) void msg_o_k(
    const float* __restrict__ Ag, const float* __restrict__ Sm, float* __restrict__ mo)
{
    __shared__ float As[NH * NN];
    const int b = blockIdx.y, t = threadIdx.x;
#pragma unroll
    for (int i = 0; i < 4; i++) As[t + 256 * i] = Ag[b * NH * NN + t + 256 * i];
    __syncthreads();
    const int j = blockIdx.x * 256 + t;
    float s[NH];
#pragma unroll
    for (int x = 0; x < NH; x++) s[x] = Sm[((long)(b * NH + x)) * 1024 + j];
    for (int n = 0; n < NN; n++) {
        float acc = 0.f;
#pragma unroll
        for (int x = 0; x < NH; x++) acc += As[x * NN + n] * s[x];
        mo[((long)(b * NN + n)) * 1024 + j] = acc;
    }
}

// ---------------- output assembly --------------------------------------------
__device__ __forceinline__ float lis_f(float s) {
    return 8.3f / (1.f + expf(12.f - 10.f * s));
}

__global__ __launch_bounds__(128) void out_kernel(
    const float* __restrict__ enc, const float* __restrict__ Ag,
    const float* __restrict__ coords, const int* __restrict__ labels,
    const float* __restrict__ scores, float* __restrict__ out)
{
    const int b = blockIdx.y, m = blockIdx.x, t = threadIdx.x;
    const int x = m / 63; const int r = m - 63 * x; const int y = r + (r >= x ? 1 : 0);
    const long row = (long)b * MM + m;

    const float4* ex = (const float4*)(enc + ((long)(b * NN + x)) * RR);
    const float4* ey = (const float4*)(enc + ((long)(b * NN + y)) * RR);
    float4* po = (float4*)(out + row * 2048);
#pragma unroll
    for (int i = 0; i < 4; i++) {
        int q = t + (i << 7);
        po[q] = (q < 256) ? ex[q] : ey[q - 256];
    }
    if (t < 4)        out[OFF_BH + row * 4 + t]       = coords[(b * NN + x) * 4 + t];
    else if (t < 8)   out[OFF_BO + row * 4 + (t - 4)] = coords[(b * NN + y) * 4 + (t - 4)];

    const int lbl = labels[b * NN + y];
    const float val = Ag[(b * NH + x) * NN + y] *
                      lis_f(scores[b * NN + x]) * lis_f(scores[b * NN + y]);
    for (int c = t; c < NCLS; c += 128)
        out[OFF_PR + row * (long)NCLS + c] = (c == lbl) ? val : 0.f;
}

// ---------------- host orchestration -----------------------------------------
extern "C" void kernel_launch(void* const* d_in, const int* in_sizes, int n_in,
                              void* d_out, int out_size)
{
    const float* box_features = (const float*)d_in[0];
    const float* box_coords   = (const float*)d_in[1];
    const int*   box_labels   = (const int*)  d_in[2];
    const float* box_scores   = (const float*)d_in[3];
    const float* W1  = (const float*)d_in[4];
    const float* b1  = (const float*)d_in[5];
    const float* W2  = (const float*)d_in[6];
    const float* b2  = (const float*)d_in[7];
    const float* W3  = (const float*)d_in[8];
    const float* b3  = (const float*)d_in[9];
    const float* Ws  = (const float*)d_in[10];
    const float* bs  = (const float*)d_in[11];
    const float* Wo  = (const float*)d_in[12];
    const float* bo  = (const float*)d_in[13];
    const float* Wsu = (const float*)d_in[14];
    const float* Wou = (const float*)d_in[15];
    float* out = (float*)d_out;

    float *encA, *encB, *UV, *O, *mh, *eh, *Sb, *mo, *Ag;
    uint32_t *W1p, *W2p, *Wop, *Wsp, *Wsup, *Woup;
    cudaGetSymbolAddress((void**)&encA, g_encA);
    cudaGetSymbolAddress((void**)&encB, g_encB);
    cudaGetSymbolAddress((void**)&UV,   g_UV);
    cudaGetSymbolAddress((void**)&O,    g_O);
    cudaGetSymbolAddress((void**)&mh,   g_mh);
    cudaGetSymbolAddress((void**)&eh,   g_eh);
    cudaGetSymbolAddress((void**)&Sb,   g_S);
    cudaGetSymbolAddress((void**)&mo,   g_mo);
    cudaGetSymbolAddress((void**)&Ag,   g_A);
    cudaGetSymbolAddress((void**)&W1p,  g_W1p);
    cudaGetSymbolAddress((void**)&W2p,  g_W2p);
    cudaGetSymbolAddress((void**)&Wop,  g_Wop);
    cudaGetSymbolAddress((void**)&Wsp,  g_Wsp);
    cudaGetSymbolAddress((void**)&Wsup, g_Wsup);
    cudaGetSymbolAddress((void**)&Woup, g_Woup);

    cudaFuncSetAttribute(gemm_bf16p,
                         cudaFuncAttributeMaxDynamicSharedMemorySize, GEMM_SMEM);
    cudaFuncSetAttribute(pair_mlp_mma,
                         cudaFuncAttributeMaxDynamicSharedMemorySize, PAIR_SMEM);

    // prepack weights (bf16 hi/lo planes, byte-neutral vs fp32)
    pack_wuv<<<512, 256>>>(W1, W1p);
    pack_w<<<256, 256>>>(W2,  W2p,  512, 512);
    pack_w<<<256, 256>>>(Wo,  Wop,  512, 1024);
    pack_w<<<256, 256>>>(Ws,  Wsp,  512, 1024);
    pack_w<<<512, 256>>>(Wsu, Wsup, 1024, 1024);
    pack_w<<<512, 256>>>(Wou, Woup, 1024, 1024);

    cudaMemcpyAsync(encA, box_features, (size_t)BB * NN * RR * 4,
                    cudaMemcpyDeviceToDevice, 0);

    const long sEnc = (long)NN * RR;   // 65536
    const long sH   = (long)NH * RR;   // 16384

    for (int it = 0; it < 2; it++) {
        float* encIn  = (it == 0) ? encA : encB;
        float* encOut = (it == 0) ? encB : encA;

        // UV = enc @ Wuv  (K=1024, N=2048)
        gemm_bf16p<<<dim3(16, 32), 256, GEMM_SMEM>>>(
            encIn, 6, sEnc, 1024, (const float*)0, 0,
            W1p, (const float*)0, UV, 2048, 512L * 2048, 2048, 1024, 0);
        // A = sigmoid(pair MLP)
        pair_mlp_mma<<<dim3(16, BB), 512, PAIR_SMEM>>>(
            UV, b1, W2p, b2, W3, b3, Ag);
        // O = relu(enc @ Wo + bo)
        gemm_bf16p<<<dim3(8, 32), 256, GEMM_SMEM>>>(
            encIn, 6, sEnc, 1024, (const float*)0, 0,
            Wop, bo, O, 1024, 512L * 1024, 1024, 1024, 1);
        // msg_h = A @ O
        msg_h_k<<<dim3(4, BB), 256>>>(Ag, O, mh);
        // enc_h = concat(enc[:16], msg_h) @ Wsu  (K=2048)
        gemm_bf16p<<<dim3(8, 8), 256, GEMM_SMEM>>>(
            encIn, 4, sEnc, 1024, mh, sH,
            Wsup, (const float*)0, eh, 1024, 1024L * 1024, 1024, 2048, 0);
        // enc[:16] = enc_h
        cudaMemcpy2DAsync(encIn, (size_t)sEnc * 4, eh, (size_t)sH * 4,
                          (size_t)sH * 4, BB, cudaMemcpyDeviceToDevice, 0);
        // S = relu(enc_h @ Ws + bs)
        gemm_bf16p<<<dim3(8, 8), 256, GEMM_SMEM>>>(
            eh, 4, sH, 1024, (const float*)0, 0,
            Wsp, bs, Sb, 1024, 512L * 1024, 1024, 1024, 1);
        // msg_o = A^T @ S
        msg_o_k<<<dim3(4, BB), 256>>>(Ag, Sb, mo);
        // encOut = concat(enc, msg_o) @ Wou  (K=2048)
        gemm_bf16p<<<dim3(8, 32), 256, GEMM_SMEM>>>(
            encIn, 6, sEnc, 1024, mo, sEnc,
            Woup, (const float*)0, encOut, 1024, 1024L * 1024, 1024, 2048, 0);
    }

    out_kernel<<<dim3(MM, BB), 128>>>(encA, Ag, box_coords, box_labels,
                                      box_scores, out);
    (void)in_sizes; (void)n_in; (void)out_size;
}

// round 9
// speedup vs baseline: 2.0798x; 1.0080x over previous
#include <cuda_runtime.h>
#include <math.h>
#include <stdint.h>

// Problem constants
#define BB   32
#define NN   64
#define NH   16
#define RR   1024
#define REP  1024
#define MM   1008
#define NCLS 117

// Output layout offsets (floats)
#define OFF_BH  66060288L
#define OFF_BO  66189312L
#define OFF_PR  66318336L

// ---------------- scratch (device globals) -----------------------------------
__device__ float g_encA[BB * NN * RR];
__device__ float g_encB[BB * NN * RR];
__device__ float g_UV [BB * NN * 2048];
__device__ float g_O  [BB * NN * REP];
__device__ float g_mh [BB * NH * REP];
__device__ float g_eh [BB * NH * RR];
__device__ float g_S  [BB * NH * REP];
__device__ float g_mo [BB * NN * REP];
__device__ float g_A  [BB * NH * NN];

// packed weights, interleaved-pair layout:
// plane p in {hi,lo}; per plane rows gr = q*4+tig (q = k/16 group), each row
// 2*N words; word at (gr, n, j) = bf16x2 of k-pair kp = q*8 + tig + 4*j.
__device__ uint32_t g_W1p [1024L * 2048];  // fused UV: K=1024, N=2048
__device__ uint32_t g_W2p [1024L * 512];   // K=1024, N=512
__device__ uint32_t g_Wop [1024L * 1024];
__device__ uint32_t g_Wsp [1024L * 1024];
__device__ uint32_t g_Wsup[2048L * 1024];  // K=2048
__device__ uint32_t g_Woup[2048L * 1024];  // K=2048

// ---------------- helpers ----------------------------------------------------
__device__ __forceinline__ void mma16(float* c, const uint32_t* a, const uint32_t* b)
{
    asm volatile(
        "mma.sync.aligned.m16n8k16.row.col.f32.bf16.bf16.f32 "
        "{%0,%1,%2,%3}, {%4,%5,%6,%7}, {%8,%9}, {%0,%1,%2,%3};\n"
        : "+f"(c[0]), "+f"(c[1]), "+f"(c[2]), "+f"(c[3])
        : "r"(a[0]), "r"(a[1]), "r"(a[2]), "r"(a[3]), "r"(b[0]), "r"(b[1]));
}

__device__ __forceinline__ uint32_t pk_hi(float x0, float x1)
{
    uint32_t r;
    asm("cvt.rn.bf16x2.f32 %0, %1, %2;" : "=r"(r) : "f"(x1), "f"(x0));
    return r;
}
__device__ __forceinline__ uint32_t pk_lo(float x0, float x1, uint32_t hi)
{
    float h0 = __uint_as_float(hi << 16);
    float h1 = __uint_as_float(hi & 0xffff0000u);
    uint32_t r;
    asm("cvt.rn.bf16x2.f32 %0, %1, %2;" : "=r"(r) : "f"(x1 - h1), "f"(x0 - h0));
    return r;
}

__device__ __forceinline__ void cpa16(void* smem, const void* gmem)
{
    uint32_t s = (uint32_t)__cvta_generic_to_shared(smem);
    asm volatile("cp.async.cg.shared.global [%0], [%1], 16;\n" :: "r"(s), "l"(gmem));
}
__device__ __forceinline__ void cp_commit()
{
    asm volatile("cp.async.commit_group;\n");
}
template <int N> __device__ __forceinline__ void cp_wait()
{
    asm volatile("cp.async.wait_group %0;\n" :: "n"(N));
}

// ---------------- weight prepack (interleaved-pair layout) --------------------
__global__ __launch_bounds__(256) void pack_w(
    const float* __restrict__ W, uint32_t* __restrict__ Wp, int Kh, int N)
{
    const long plane = (long)Kh * N;
    const long total = 2 * plane;
    const int rowlen = 2 * N;
    for (long i = blockIdx.x * blockDim.x + threadIdx.x; i < total;
         i += (long)gridDim.x * blockDim.x) {
        int p = (int)(i / plane);
        long rem = i - (long)p * plane;
        int row = (int)(rem / rowlen);
        int col2 = (int)(rem - (long)row * rowlen);
        int n = col2 >> 1, j = col2 & 1;
        int q = row >> 2, tig = row & 3;
        int kp = q * 8 + tig + 4 * j;
        float x0 = W[(long)(2 * kp) * N + n];
        float x1 = W[(long)(2 * kp + 1) * N + n];
        uint32_t hi = pk_hi(x0, x1);
        Wp[i] = p ? pk_lo(x0, x1, hi) : hi;
    }
}

// fused UV pack: Wuv(k, c) = c<1024 ? W1[k][c] : W1[1024+k][c-1024], K=1024, N=2048
__global__ __launch_bounds__(256) void pack_wuv(
    const float* __restrict__ W1, uint32_t* __restrict__ Wp)
{
    const long plane = 512L * 2048;
    const long total = 2 * plane;
    for (long i = blockIdx.x * blockDim.x + threadIdx.x; i < total;
         i += (long)gridDim.x * blockDim.x) {
        int p = (int)(i / plane);
        long rem = i - (long)p * plane;
        int row = (int)(rem >> 12);          // / 4096
        int col2 = (int)(rem & 4095);
        int n = col2 >> 1, j = col2 & 1;
        int q = row >> 2, tig = row & 3;
        int kp = q * 8 + tig + 4 * j;
        int k0 = 2 * kp, k1 = 2 * kp + 1;
        float x0, x1;
        if (n < 1024) {
            x0 = W1[(long)k0 * 1024 + n];
            x1 = W1[(long)k1 * 1024 + n];
        } else {
            x0 = W1[(long)(1024 + k0) * 1024 + (n - 1024)];
            x1 = W1[(long)(1024 + k1) * 1024 + (n - 1024)];
        }
        uint32_t hi = pk_hi(x0, x1);
        Wp[i] = p ? pk_lo(x0, x1, hi) : hi;
    }
}

// ---------------- batched GEMM (3xBF16, interleaved W, LDS.64 B frags) --------
// A flat row r -> (b = r>>lrpb, n = r&mask); optional K-concat A2; optional
// per-row override A1o for rows n<16 (stride 16384). BM=64, BN=128, BK=32.
// smem: A [2][2][64][20] = 5120 w; B [2][2][8][264] = 8448 w.
#define GEMM_SMEM ((5120 + 8448) * 4)
__global__ __launch_bounds__(256, 2) void gemm_bf16p(
    const float* __restrict__ A1, const float* __restrict__ A1o,
    int lrpb, long sA1, int K1,
    const float* __restrict__ A2, long sA2,
    const uint32_t* __restrict__ Wp, const float* __restrict__ bias,
    float* __restrict__ C, int Nw, long PKw, int ldc, int Ktot, int do_relu)
{
    extern __shared__ __align__(16) uint32_t sm[];
    uint32_t* As = sm;          // A planes
    uint32_t* Bs = sm + 5120;   // B planes

    const int t = threadIdx.x, lane = t & 31, warp = t >> 5;
    const int gid = lane >> 2, tig = lane & 3;
    const int wm = warp >> 2, wn = warp & 3;
    const int m0 = wm * 32, n0w = wn * 32;
    const long bn0 = (long)blockIdx.x * 128;
    const int bm0 = blockIdx.y * 64;
    const int K2 = Ktot - K1;
    const int rmask = (1 << lrpb) - 1;

    const int lrow = t >> 2, lf4 = t & 3;
    const int grow = bm0 + lrow;
    const int b = grow >> lrpb, n = grow & rmask;
    const float* p1 = (A1o && n < 16)
                        ? (A1o + (long)b * 16384 + (long)n * 1024)
                        : (A1 + (long)b * sA1 + (long)n * K1);
    const float* p2 = A2 ? (A2 + (long)b * sA2 + (long)n * K2) : p1;

    float4 ra0, ra1;
    auto ldgA = [&](int k0) {
        const float* rp = (k0 < K1) ? (p1 + k0) : (p2 + (k0 - K1));
        ra0 = *(const float4*)(rp + lf4 * 4);
        ra1 = *(const float4*)(rp + lf4 * 4 + 16);
    };
    auto stsA = [&](int buf) {
        uint32_t* Ah = As + buf * 2560 + lrow * 20;
        uint32_t* Al = Ah + 1280;
        const int w = lf4 * 2;
        uint32_t h0 = pk_hi(ra0.x, ra0.y), h1 = pk_hi(ra0.z, ra0.w);
        uint32_t h2 = pk_hi(ra1.x, ra1.y), h3 = pk_hi(ra1.z, ra1.w);
        Ah[w] = h0; Ah[w + 1] = h1; Ah[w + 8] = h2; Ah[w + 9] = h3;
        Al[w]     = pk_lo(ra0.x, ra0.y, h0);
        Al[w + 1] = pk_lo(ra0.z, ra0.w, h1);
        Al[w + 8] = pk_lo(ra1.x, ra1.y, h2);
        Al[w + 9] = pk_lo(ra1.z, ra1.w, h3);
    };
    auto stageB = [&](int buf, int k0) {
        const int gr0 = k0 >> 2;
#pragma unroll
        for (int i = 0; i < 4; i++) {
            int f = t + i * 256;                 // 0..1023
            int plane = f >> 9, g = f & 511;
            int rl = g >> 6, c4 = (g & 63) * 4;
            cpa16(&Bs[buf * 4224 + plane * 2112 + rl * 264 + c4],
                  Wp + plane * PKw + (long)(gr0 + rl) * (2 * Nw) + bn0 * 2 + c4);
        }
        cp_commit();
    };

    float c[2][4][4];
#pragma unroll
    for (int mt = 0; mt < 2; mt++)
#pragma unroll
        for (int nt = 0; nt < 4; nt++)
#pragma unroll
            for (int e = 0; e < 4; e++) c[mt][nt][e] = 0.f;

    ldgA(0); stageB(0, 0); stsA(0);
    int buf = 0;
    for (int k0 = 0; k0 < Ktot; k0 += 32) {
        const bool more = (k0 + 32 < Ktot);
        cp_wait<0>();
        __syncthreads();
        if (more) { ldgA(k0 + 32); stageB(buf ^ 1, k0 + 32); }

        const uint32_t* Ah = As + buf * 2560;
        const uint32_t* Al = Ah + 1280;
        const uint32_t* Bh = Bs + buf * 4224;
        const uint32_t* Bl = Bh + 2112;
#pragma unroll
        for (int k16 = 0; k16 < 2; k16++) {
            const int kb = k16 * 8;
            uint32_t ah[2][4], al[2][4];
#pragma unroll
            for (int mt = 0; mt < 2; mt++) {
                int r0 = (m0 + mt * 16 + gid) * 20;
                int r1 = r0 + 160;
                ah[mt][0] = Ah[r0 + kb + tig];
                ah[mt][1] = Ah[r1 + kb + tig];
                ah[mt][2] = Ah[r0 + kb + tig + 4];
                ah[mt][3] = Ah[r1 + kb + tig + 4];
                al[mt][0] = Al[r0 + kb + tig];
                al[mt][1] = Al[r1 + kb + tig];
                al[mt][2] = Al[r0 + kb + tig + 4];
                al[mt][3] = Al[r1 + kb + tig + 4];
            }
            const int brow = (k16 * 4 + tig) * 264;
#pragma unroll
            for (int nt = 0; nt < 4; nt++) {
                int cw = brow + 2 * (n0w + nt * 8 + gid);
                uint2 b2h = *(const uint2*)&Bh[cw];
                uint2 b2l = *(const uint2*)&Bl[cw];
                uint32_t bh[2] = { b2h.x, b2h.y };
                uint32_t bl[2] = { b2l.x, b2l.y };
#pragma unroll
                for (int mt = 0; mt < 2; mt++) {
                    mma16(c[mt][nt], ah[mt], bh);
                    mma16(c[mt][nt], ah[mt], bl);
                    mma16(c[mt][nt], al[mt], bh);
                }
            }
        }
        if (more) stsA(buf ^ 1);
        buf ^= 1;
    }

#pragma unroll
    for (int mt = 0; mt < 2; mt++) {
#pragma unroll
        for (int nt = 0; nt < 4; nt++) {
            long col = bn0 + n0w + nt * 8 + 2 * tig;
            float b0v = 0.f, b1v = 0.f;
            if (bias) { b0v = bias[col]; b1v = bias[col + 1]; }
            int r = bm0 + m0 + mt * 16 + gid;
            float v0 = c[mt][nt][0] + b0v, v1 = c[mt][nt][1] + b1v;
            float v2 = c[mt][nt][2] + b0v, v3 = c[mt][nt][3] + b1v;
            if (do_relu) {
                v0 = fmaxf(v0, 0.f); v1 = fmaxf(v1, 0.f);
                v2 = fmaxf(v2, 0.f); v3 = fmaxf(v3, 0.f);
            }
            *(float2*)&C[(long)r * ldc + col]       = make_float2(v0, v1);
            *(float2*)&C[(long)(r + 8) * ldc + col] = make_float2(v2, v3);
        }
    }
}

// ---------------- fused pair MLP (3xBF16, interleaved W2, LDS.64 B) -----------
// BM=64 pairs, BN=512, BK=32, 512 threads. grid (16, 32).
// smem: A 5120 w; B [2][2][8][1032] = 33024 w; wpart 512 w.
#define PAIR_SMEM ((5120 + 33024 + 512) * 4)
__global__ __launch_bounds__(512, 1) void pair_mlp_mma(
    const float* __restrict__ UV, const float* __restrict__ b1,
    const uint32_t* __restrict__ W2p, const float* __restrict__ b2,
    const float* __restrict__ W3, const float* __restrict__ b3,
    float* __restrict__ Aout)
{
    extern __shared__ __align__(16) uint32_t sm[];
    uint32_t* As = sm;
    uint32_t* Bs = sm + 5120;
    float* wpart = (float*)(sm + 5120 + 33024);

    const int t = threadIdx.x, lane = t & 31, warp = t >> 5;
    const int gid = lane >> 2, tig = lane & 3;
    const int wm = warp >> 3, wn = warp & 7;
    const int m0 = wm * 32, n0w = wn * 64;
    const int bi = blockIdx.y;
    const long PK2 = 512L * 512;

    const int lr = t >> 3, k4 = (t & 7) * 4;
    const int mld = blockIdx.x * 64 + lr;
    const int valid = (mld < MM);
    int xl = 0, yl = 0;
    if (valid) { xl = mld / 63; int rl = mld - 63 * xl; yl = rl + (rl >= xl ? 1 : 0); }
    const float* Urow = UV + ((long)(bi * 64 + xl)) * 2048;
    const float* Vrow = UV + ((long)(bi * 64 + yl)) * 2048 + 1024;

    float4 ru, rv, rb;
    auto ldgA = [&](int k0) {
        ru = *(const float4*)(Urow + k0 + k4);
        rv = *(const float4*)(Vrow + k0 + k4);
        rb = *(const float4*)(b1 + k0 + k4);
    };
    auto stsA = [&](int buf) {
        float4 h;
        h.x = fmaxf(ru.x + rv.x + rb.x, 0.f);
        h.y = fmaxf(ru.y + rv.y + rb.y, 0.f);
        h.z = fmaxf(ru.z + rv.z + rb.z, 0.f);
        h.w = fmaxf(ru.w + rv.w + rb.w, 0.f);
        if (!valid) h = make_float4(0.f, 0.f, 0.f, 0.f);
        uint32_t* Ah = As + buf * 2560 + lr * 20;
        uint32_t* Al = Ah + 1280;
        const int w = (t & 7) * 2;
        uint32_t h0 = pk_hi(h.x, h.y), h1 = pk_hi(h.z, h.w);
        Ah[w] = h0; Ah[w + 1] = h1;
        Al[w]     = pk_lo(h.x, h.y, h0);
        Al[w + 1] = pk_lo(h.z, h.w, h1);
    };
    auto stageB = [&](int buf, int k0) {
        const int gr0 = k0 >> 2;
#pragma unroll
        for (int i = 0; i < 8; i++) {
            int f = t + i * 512;                // 0..4095
            int plane = f >> 11, g = f & 2047;
            int rl = g >> 8, c4 = (g & 255) * 4;
            cpa16(&Bs[buf * 16512 + plane * 8256 + rl * 1032 + c4],
                  W2p + plane * PK2 + (long)(gr0 + rl) * 1024 + c4);
        }
        cp_commit();
    };

    float c[2][8][4];
#pragma unroll
    for (int mt = 0; mt < 2; mt++)
#pragma unroll
        for (int nt = 0; nt < 8; nt++)
#pragma unroll
            for (int e = 0; e < 4; e++) c[mt][nt][e] = 0.f;

    ldgA(0); stageB(0, 0); stsA(0);
    int buf = 0;
    for (int k0 = 0; k0 < REP; k0 += 32) {
        const bool more = (k0 + 32 < REP);
        cp_wait<0>();
        __syncthreads();
        if (more) { ldgA(k0 + 32); stageB(buf ^ 1, k0 + 32); }

        const uint32_t* Ah = As + buf * 2560;
        const uint32_t* Al = Ah + 1280;
        const uint32_t* Bh = Bs + buf * 16512;
        const uint32_t* Bl = Bh + 8256;
#pragma unroll
        for (int k16 = 0; k16 < 2; k16++) {
            const int kb = k16 * 8;
            uint32_t ah[2][4], al[2][4];
#pragma unroll
            for (int mt = 0; mt < 2; mt++) {
                int r0 = (m0 + mt * 16 + gid) * 20;
                int r1 = r0 + 160;
                ah[mt][0] = Ah[r0 + kb + tig];
                ah[mt][1] = Ah[r1 + kb + tig];
                ah[mt][2] = Ah[r0 + kb + tig + 4];
                ah[mt][3] = Ah[r1 + kb + tig + 4];
                al[mt][0] = Al[r0 + kb + tig];
                al[mt][1] = Al[r1 + kb + tig];
                al[mt][2] = Al[r0 + kb + tig + 4];
                al[mt][3] = Al[r1 + kb + tig + 4];
            }
            const int brow = (k16 * 4 + tig) * 1032;
#pragma unroll
            for (int nt = 0; nt < 8; nt++) {
                int cw = brow + 2 * (n0w + nt * 8 + gid);
                uint2 b2h = *(const uint2*)&Bh[cw];
                uint2 b2l = *(const uint2*)&Bl[cw];
                uint32_t bh[2] = { b2h.x, b2h.y };
                uint32_t bl[2] = { b2l.x, b2l.y };
#pragma unroll
                for (int mt = 0; mt < 2; mt++) {
                    mma16(c[mt][nt], ah[mt], bh);
                    mma16(c[mt][nt], ah[mt], bl);
                    mma16(c[mt][nt], al[mt], bh);
                }
            }
        }
        if (more) stsA(buf ^ 1);
        buf ^= 1;
    }

    // epilogue: h2 = relu(c + b2); partial w = h2 @ W3
    float rp[4] = { 0.f, 0.f, 0.f, 0.f };
#pragma unroll
    for (int mt = 0; mt < 2; mt++) {
#pragma unroll
        for (int nt = 0; nt < 8; nt++) {
            int col = n0w + nt * 8 + 2 * tig;
            float b2a = b2[col], b2b = b2[col + 1];
            float w3a = W3[col], w3b = W3[col + 1];
            rp[2 * mt + 0] += fmaxf(c[mt][nt][0] + b2a, 0.f) * w3a
                            + fmaxf(c[mt][nt][1] + b2b, 0.f) * w3b;
            rp[2 * mt + 1] += fmaxf(c[mt][nt][2] + b2a, 0.f) * w3a
                            + fmaxf(c[mt][nt][3] + b2b, 0.f) * w3b;
        }
    }
#pragma unroll
    for (int e = 0; e < 4; e++) {
        float v = rp[e];
        v += __shfl_xor_sync(0xffffffffu, v, 1);
        v += __shfl_xor_sync(0xffffffffu, v, 2);
        int mt = e >> 1, o = e & 1;
        if (tig == 0) wpart[(m0 + mt * 16 + o * 8 + gid) * 8 + wn] = v;
    }
    __syncthreads();
    if (t < 64) {
        float s = b3[0];
#pragma unroll
        for (int w = 0; w < 8; w++) s += wpart[t * 8 + w];
        int m = blockIdx.x * 64 + t;
        if (m < MM) {
            int x = m / 63; int r = m - 63 * x; int y = r + (r >= x ? 1 : 0);
            Aout[(bi * 16 + x) * 64 + y] = 1.f / (1.f + expf(-s));
        }
    }
}

// ---------------- msg_h = A @ O ------------------------------------------------
__global__ __launch_bounds__(256) void msg_h_k(
    const float* __restrict__ Ag, const float* __restrict__ O, float* __restrict__ mh)
{
    __shared__ float As[NH * NN];
    const int b = blockIdx.y, t = threadIdx.x;
#pragma unroll
    for (int i = 0; i < 4; i++) As[t + 256 * i] = Ag[b * NH * NN + t + 256 * i];
    __syncthreads();
    const int j = blockIdx.x * 256 + t;
    float acc[NH];
#pragma unroll
    for (int x = 0; x < NH; x++) acc[x] = 0.f;
    for (int n = 0; n < NN; n++) {
        float o = O[((long)(b * NN + n)) * 1024 + j];
#pragma unroll
        for (int x = 0; x < NH; x++) acc[x] += As[x * NN + n] * o;
    }
#pragma unroll
    for (int x = 0; x < NH; x++) mh[((long)(b * NH + x)) * 1024 + j] = acc[x];
}

// ---------------- msg_o = A^T @ S ----------------------------------------------
__global__ __launch_bounds__(256) void msg_o_k(
    const float* __restrict__ Ag, const float* __restrict__ Sm, float* __restrict__ mo)
{
    __shared__ float As[NH * NN];
    const int b = blockIdx.y, t = threadIdx.x;
#pragma unroll
    for (int i = 0; i < 4; i++) As[t + 256 * i] = Ag[b * NH * NN + t + 256 * i];
    __syncthreads();
    const int j = blockIdx.x * 256 + t;
    float s[NH];
#pragma unroll
    for (int x = 0; x < NH; x++) s[x] = Sm[((long)(b * NH + x)) * 1024 + j];
    for (int n = 0; n < NN; n++) {
        float acc = 0.f;
#pragma unroll
        for (int x = 0; x < NH; x++) acc += As[x * NN + n] * s[x];
        mo[((long)(b * NN + n)) * 1024 + j] = acc;
    }
}

// ---------------- output assembly ----------------------------------------------
__device__ __forceinline__ float lis_f(float s) {
    return 8.3f / (1.f + expf(12.f - 10.f * s));
}

__global__ __launch_bounds__(128) void out_kernel(
    const float* __restrict__ enc, const float* __restrict__ Ag,
    const float* __restrict__ coords, const int* __restrict__ labels,
    const float* __restrict__ scores, float* __restrict__ out)
{
    const int b = blockIdx.y, m = blockIdx.x, t = threadIdx.x;
    const int x = m / 63; const int r = m - 63 * x; const int y = r + (r >= x ? 1 : 0);
    const long row = (long)b * MM + m;

    const float4* ex = (const float4*)(enc + ((long)(b * NN + x)) * RR);
    const float4* ey = (const float4*)(enc + ((long)(b * NN + y)) * RR);
    float4* po = (float4*)(out + row * 2048);
#pragma unroll
    for (int i = 0; i < 4; i++) {
        int q = t + (i << 7);
        po[q] = (q < 256) ? ex[q] : ey[q - 256];
    }
    if (t < 4)        out[OFF_BH + row * 4 + t]       = coords[(b * NN + x) * 4 + t];
    else if (t < 8)   out[OFF_BO + row * 4 + (t - 4)] = coords[(b * NN + y) * 4 + (t - 4)];

    const int lbl = labels[b * NN + y];
    const float val = Ag[(b * NH + x) * NN + y] *
                      lis_f(scores[b * NN + x]) * lis_f(scores[b * NN + y]);
    for (int c = t; c < NCLS; c += 128)
        out[OFF_PR + row * (long)NCLS + c] = (c == lbl) ? val : 0.f;
}

// ---------------- host orchestration -------------------------------------------
extern "C" void kernel_launch(void* const* d_in, const int* in_sizes, int n_in,
                              void* d_out, int out_size)
{
    const float* box_features = (const float*)d_in[0];
    const float* box_coords   = (const float*)d_in[1];
    const int*   box_labels   = (const int*)  d_in[2];
    const float* box_scores   = (const float*)d_in[3];
    const float* W1  = (const float*)d_in[4];
    const float* b1  = (const float*)d_in[5];
    const float* W2  = (const float*)d_in[6];
    const float* b2  = (const float*)d_in[7];
    const float* W3  = (const float*)d_in[8];
    const float* b3  = (const float*)d_in[9];
    const float* Ws  = (const float*)d_in[10];
    const float* bs  = (const float*)d_in[11];
    const float* Wo  = (const float*)d_in[12];
    const float* bo  = (const float*)d_in[13];
    const float* Wsu = (const float*)d_in[14];
    const float* Wou = (const float*)d_in[15];
    float* out = (float*)d_out;

    float *encA, *encB, *UV, *O, *mh, *eh, *Sb, *mo, *Ag;
    uint32_t *W1p, *W2p, *Wop, *Wsp, *Wsup, *Woup;
    cudaGetSymbolAddress((void**)&encA, g_encA);
    cudaGetSymbolAddress((void**)&encB, g_encB);
    cudaGetSymbolAddress((void**)&UV,   g_UV);
    cudaGetSymbolAddress((void**)&O,    g_O);
    cudaGetSymbolAddress((void**)&mh,   g_mh);
    cudaGetSymbolAddress((void**)&eh,   g_eh);
    cudaGetSymbolAddress((void**)&Sb,   g_S);
    cudaGetSymbolAddress((void**)&mo,   g_mo);
    cudaGetSymbolAddress((void**)&Ag,   g_A);
    cudaGetSymbolAddress((void**)&W1p,  g_W1p);
    cudaGetSymbolAddress((void**)&W2p,  g_W2p);
    cudaGetSymbolAddress((void**)&Wop,  g_Wop);
    cudaGetSymbolAddress((void**)&Wsp,  g_Wsp);
    cudaGetSymbolAddress((void**)&Wsup, g_Wsup);
    cudaGetSymbolAddress((void**)&Woup, g_Woup);

    cudaFuncSetAttribute(gemm_bf16p,
                         cudaFuncAttributeMaxDynamicSharedMemorySize, GEMM_SMEM);
    cudaFuncSetAttribute(pair_mlp_mma,
                         cudaFuncAttributeMaxDynamicSharedMemorySize, PAIR_SMEM);

    // prepack weights (interleaved-pair bf16 hi/lo layout)
    pack_wuv<<<512, 256>>>(W1, W1p);
    pack_w<<<256, 256>>>(W2,  W2p,  512, 512);
    pack_w<<<256, 256>>>(Wo,  Wop,  512, 1024);
    pack_w<<<256, 256>>>(Ws,  Wsp,  512, 1024);
    pack_w<<<512, 256>>>(Wsu, Wsup, 1024, 1024);
    pack_w<<<512, 256>>>(Wou, Woup, 1024, 1024);

    cudaMemcpyAsync(encA, box_features, (size_t)BB * NN * RR * 4,
                    cudaMemcpyDeviceToDevice, 0);

    const long sEnc = (long)NN * RR;   // 65536
    const long sH   = (long)NH * RR;   // 16384
    const float* NUL = (const float*)0;

    for (int it = 0; it < 2; it++) {
        float* encIn  = (it == 0) ? encA : encB;
        float* encOut = (it == 0) ? encB : encA;

        // UV = enc @ Wuv  (K=1024, N=2048)
        gemm_bf16p<<<dim3(16, 32), 256, GEMM_SMEM>>>(
            encIn, NUL, 6, sEnc, 1024, NUL, 0,
            W1p, NUL, UV, 2048, 512L * 2048, 2048, 1024, 0);
        // A = sigmoid(pair MLP)
        pair_mlp_mma<<<dim3(16, BB), 512, PAIR_SMEM>>>(
            UV, b1, W2p, b2, W3, b3, Ag);
        // O = relu(enc @ Wo + bo)
        gemm_bf16p<<<dim3(8, 32), 256, GEMM_SMEM>>>(
            encIn, NUL, 6, sEnc, 1024, NUL, 0,
            Wop, bo, O, 1024, 512L * 1024, 1024, 1024, 1);
        // msg_h = A @ O
        msg_h_k<<<dim3(4, BB), 256>>>(Ag, O, mh);
        // enc_h = concat(enc[:16], msg_h) @ Wsu  (K=2048)
        gemm_bf16p<<<dim3(8, 8), 256, GEMM_SMEM>>>(
            encIn, NUL, 4, sEnc, 1024, mh, sH,
            Wsup, NUL, eh, 1024, 1024L * 1024, 1024, 2048, 0);
        // S = relu(enc_h @ Ws + bs)
        gemm_bf16p<<<dim3(8, 8), 256, GEMM_SMEM>>>(
            eh, NUL, 4, sH, 1024, NUL, 0,
            Wsp, bs, Sb, 1024, 512L * 1024, 1024, 1024, 1);
        // msg_o = A^T @ S
        msg_o_k<<<dim3(4, BB), 256>>>(Ag, Sb, mo);
        // encOut = concat(spliced enc, msg_o) @ Wou  (K=2048)
        // splice handled via A1o override: rows n<16 read eh instead of encIn
        gemm_bf16p<<<dim3(8, 32), 256, GEMM_SMEM>>>(
            encIn, eh, 6, sEnc, 1024, mo, sEnc,
            Woup, NUL, encOut, 1024, 1024L * 1024, 1024, 2048, 0);
    }

    out_kernel<<<dim3(MM, BB), 128>>>(encA, Ag, box_coords, box_labels,
                                      box_scores, out);
    (void)in_sizes; (void)n_in; (void)out_size;
}

// round 10
// speedup vs baseline: 2.1646x; 1.0408x over previous
#include <cuda_runtime.h>
#include <math.h>
#include <stdint.h>

// Problem constants
#define BB   32
#define NN   64
#define NH   16
#define RR   1024
#define REP  1024
#define MM   1008
#define NCLS 117

// Output layout offsets (floats)
#define OFF_BH  66060288L
#define OFF_BO  66189312L
#define OFF_PR  66318336L

// ---------------- scratch (device globals) -----------------------------------
__device__ float g_encA[BB * NN * RR];
__device__ float g_encB[BB * NN * RR];
__device__ float g_UV [BB * NN * 2048];
__device__ float g_O  [BB * NN * REP];
__device__ float g_mh [BB * NH * REP];
__device__ float g_eh [BB * NH * RR];
__device__ float g_S  [BB * NH * REP];
__device__ float g_mo [BB * NN * REP];
__device__ float g_A  [BB * NH * NN];

// packed weights, interleaved-pair layout (see pack_w)
__device__ uint32_t g_W1p [1024L * 2048];
__device__ uint32_t g_W2p [1024L * 512];
__device__ uint32_t g_Wop [1024L * 1024];
__device__ uint32_t g_Wsp [1024L * 1024];
__device__ uint32_t g_Wsup[2048L * 1024];
__device__ uint32_t g_Woup[2048L * 1024];

// ---------------- helpers ----------------------------------------------------
__device__ __forceinline__ void mma16(float* c, const uint32_t* a, const uint32_t* b)
{
    asm volatile(
        "mma.sync.aligned.m16n8k16.row.col.f32.bf16.bf16.f32 "
        "{%0,%1,%2,%3}, {%4,%5,%6,%7}, {%8,%9}, {%0,%1,%2,%3};\n"
        : "+f"(c[0]), "+f"(c[1]), "+f"(c[2]), "+f"(c[3])
        : "r"(a[0]), "r"(a[1]), "r"(a[2]), "r"(a[3]), "r"(b[0]), "r"(b[1]));
}

__device__ __forceinline__ uint32_t pk_hi(float x0, float x1)
{
    uint32_t r;
    asm("cvt.rn.bf16x2.f32 %0, %1, %2;" : "=r"(r) : "f"(x1), "f"(x0));
    return r;
}
__device__ __forceinline__ uint32_t pk_lo(float x0, float x1, uint32_t hi)
{
    float h0 = __uint_as_float(hi << 16);
    float h1 = __uint_as_float(hi & 0xffff0000u);
    uint32_t r;
    asm("cvt.rn.bf16x2.f32 %0, %1, %2;" : "=r"(r) : "f"(x1 - h1), "f"(x0 - h0));
    return r;
}

__device__ __forceinline__ void cpa16(void* smem, const void* gmem)
{
    uint32_t s = (uint32_t)__cvta_generic_to_shared(smem);
    asm volatile("cp.async.cg.shared.global [%0], [%1], 16;\n" :: "r"(s), "l"(gmem));
}
__device__ __forceinline__ void cp_commit()
{
    asm volatile("cp.async.commit_group;\n");
}
template <int N> __device__ __forceinline__ void cp_wait()
{
    asm volatile("cp.async.wait_group %0;\n" :: "n"(N));
}

// ---------------- weight prepack (interleaved-pair layout) --------------------
__global__ __launch_bounds__(256) void pack_w(
    const float* __restrict__ W, uint32_t* __restrict__ Wp, int Kh, int N)
{
    const long plane = (long)Kh * N;
    const long total = 2 * plane;
    const int rowlen = 2 * N;
    for (long i = blockIdx.x * blockDim.x + threadIdx.x; i < total;
         i += (long)gridDim.x * blockDim.x) {
        int p = (int)(i / plane);
        long rem = i - (long)p * plane;
        int row = (int)(rem / rowlen);
        int col2 = (int)(rem - (long)row * rowlen);
        int n = col2 >> 1, j = col2 & 1;
        int q = row >> 2, tig = row & 3;
        int kp = q * 8 + tig + 4 * j;
        float x0 = W[(long)(2 * kp) * N + n];
        float x1 = W[(long)(2 * kp + 1) * N + n];
        uint32_t hi = pk_hi(x0, x1);
        Wp[i] = p ? pk_lo(x0, x1, hi) : hi;
    }
}

// fused UV pack: Wuv(k, c) = c<1024 ? W1[k][c] : W1[1024+k][c-1024]
__global__ __launch_bounds__(256) void pack_wuv(
    const float* __restrict__ W1, uint32_t* __restrict__ Wp)
{
    const long plane = 512L * 2048;
    const long total = 2 * plane;
    for (long i = blockIdx.x * blockDim.x + threadIdx.x; i < total;
         i += (long)gridDim.x * blockDim.x) {
        int p = (int)(i / plane);
        long rem = i - (long)p * plane;
        int row = (int)(rem >> 12);
        int col2 = (int)(rem & 4095);
        int n = col2 >> 1, j = col2 & 1;
        int q = row >> 2, tig = row & 3;
        int kp = q * 8 + tig + 4 * j;
        int k0 = 2 * kp, k1 = 2 * kp + 1;
        float x0, x1;
        if (n < 1024) {
            x0 = W1[(long)k0 * 1024 + n];
            x1 = W1[(long)k1 * 1024 + n];
        } else {
            x0 = W1[(long)(1024 + k0) * 1024 + (n - 1024)];
            x1 = W1[(long)(1024 + k1) * 1024 + (n - 1024)];
        }
        uint32_t hi = pk_hi(x0, x1);
        Wp[i] = p ? pk_lo(x0, x1, hi) : hi;
    }
}

// ---------------- batched GEMM (3xBF16, interleaved W, LDS.64 B frags) --------
#define GEMM_SMEM ((5120 + 8448) * 4)
__global__ __launch_bounds__(256, 2) void gemm_bf16p(
    const float* __restrict__ A1, const float* __restrict__ A1o,
    int lrpb, long sA1, int K1,
    const float* __restrict__ A2, long sA2,
    const uint32_t* __restrict__ Wp, const float* __restrict__ bias,
    float* __restrict__ C, int Nw, long PKw, int ldc, int Ktot, int do_relu)
{
    extern __shared__ __align__(16) uint32_t sm[];
    uint32_t* As = sm;
    uint32_t* Bs = sm + 5120;

    const int t = threadIdx.x, lane = t & 31, warp = t >> 5;
    const int gid = lane >> 2, tig = lane & 3;
    const int wm = warp >> 2, wn = warp & 3;
    const int m0 = wm * 32, n0w = wn * 32;
    const long bn0 = (long)blockIdx.x * 128;
    const int bm0 = blockIdx.y * 64;
    const int K2 = Ktot - K1;
    const int rmask = (1 << lrpb) - 1;

    const int lrow = t >> 2, lf4 = t & 3;
    const int grow = bm0 + lrow;
    const int b = grow >> lrpb, n = grow & rmask;
    const float* p1 = (A1o && n < 16)
                        ? (A1o + (long)b * 16384 + (long)n * 1024)
                        : (A1 + (long)b * sA1 + (long)n * K1);
    const float* p2 = A2 ? (A2 + (long)b * sA2 + (long)n * K2) : p1;

    float4 ra0, ra1;
    auto ldgA = [&](int k0) {
        const float* rp = (k0 < K1) ? (p1 + k0) : (p2 + (k0 - K1));
        ra0 = *(const float4*)(rp + lf4 * 4);
        ra1 = *(const float4*)(rp + lf4 * 4 + 16);
    };
    auto stsA = [&](int buf) {
        uint32_t* Ah = As + buf * 2560 + lrow * 20;
        uint32_t* Al = Ah + 1280;
        const int w = lf4 * 2;
        uint32_t h0 = pk_hi(ra0.x, ra0.y), h1 = pk_hi(ra0.z, ra0.w);
        uint32_t h2 = pk_hi(ra1.x, ra1.y), h3 = pk_hi(ra1.z, ra1.w);
        Ah[w] = h0; Ah[w + 1] = h1; Ah[w + 8] = h2; Ah[w + 9] = h3;
        Al[w]     = pk_lo(ra0.x, ra0.y, h0);
        Al[w + 1] = pk_lo(ra0.z, ra0.w, h1);
        Al[w + 8] = pk_lo(ra1.x, ra1.y, h2);
        Al[w + 9] = pk_lo(ra1.z, ra1.w, h3);
    };
    auto stageB = [&](int buf, int k0) {
        const int gr0 = k0 >> 2;
#pragma unroll
        for (int i = 0; i < 4; i++) {
            int f = t + i * 256;
            int plane = f >> 9, g = f & 511;
            int rl = g >> 6, c4 = (g & 63) * 4;
            cpa16(&Bs[buf * 4224 + plane * 2112 + rl * 264 + c4],
                  Wp + plane * PKw + (long)(gr0 + rl) * (2 * Nw) + bn0 * 2 + c4);
        }
        cp_commit();
    };

    float c[2][4][4];
#pragma unroll
    for (int mt = 0; mt < 2; mt++)
#pragma unroll
        for (int nt = 0; nt < 4; nt++)
#pragma unroll
            for (int e = 0; e < 4; e++) c[mt][nt][e] = 0.f;

    ldgA(0); stageB(0, 0); stsA(0);
    int buf = 0;
    for (int k0 = 0; k0 < Ktot; k0 += 32) {
        const bool more = (k0 + 32 < Ktot);
        cp_wait<0>();
        __syncthreads();
        if (more) { ldgA(k0 + 32); stageB(buf ^ 1, k0 + 32); }

        const uint32_t* Ah = As + buf * 2560;
        const uint32_t* Al = Ah + 1280;
        const uint32_t* Bh = Bs + buf * 4224;
        const uint32_t* Bl = Bh + 2112;
#pragma unroll
        for (int k16 = 0; k16 < 2; k16++) {
            const int kb = k16 * 8;
            uint32_t ah[2][4], al[2][4];
#pragma unroll
            for (int mt = 0; mt < 2; mt++) {
                int r0 = (m0 + mt * 16 + gid) * 20;
                int r1 = r0 + 160;
                ah[mt][0] = Ah[r0 + kb + tig];
                ah[mt][1] = Ah[r1 + kb + tig];
                ah[mt][2] = Ah[r0 + kb + tig + 4];
                ah[mt][3] = Ah[r1 + kb + tig + 4];
                al[mt][0] = Al[r0 + kb + tig];
                al[mt][1] = Al[r1 + kb + tig];
                al[mt][2] = Al[r0 + kb + tig + 4];
                al[mt][3] = Al[r1 + kb + tig + 4];
            }
            const int brow = (k16 * 4 + tig) * 264;
#pragma unroll
            for (int nt = 0; nt < 4; nt++) {
                int cw = brow + 2 * (n0w + nt * 8 + gid);
                uint2 b2h = *(const uint2*)&Bh[cw];
                uint2 b2l = *(const uint2*)&Bl[cw];
                uint32_t bh[2] = { b2h.x, b2h.y };
                uint32_t bl[2] = { b2l.x, b2l.y };
#pragma unroll
                for (int mt = 0; mt < 2; mt++) {
                    mma16(c[mt][nt], ah[mt], bh);
                    mma16(c[mt][nt], ah[mt], bl);
                    mma16(c[mt][nt], al[mt], bh);
                }
            }
        }
        if (more) stsA(buf ^ 1);
        buf ^= 1;
    }

#pragma unroll
    for (int mt = 0; mt < 2; mt++) {
#pragma unroll
        for (int nt = 0; nt < 4; nt++) {
            long col = bn0 + n0w + nt * 8 + 2 * tig;
            float b0v = 0.f, b1v = 0.f;
            if (bias) { b0v = bias[col]; b1v = bias[col + 1]; }
            int r = bm0 + m0 + mt * 16 + gid;
            float v0 = c[mt][nt][0] + b0v, v1 = c[mt][nt][1] + b1v;
            float v2 = c[mt][nt][2] + b0v, v3 = c[mt][nt][3] + b1v;
            if (do_relu) {
                v0 = fmaxf(v0, 0.f); v1 = fmaxf(v1, 0.f);
                v2 = fmaxf(v2, 0.f); v3 = fmaxf(v3, 0.f);
            }
            *(float2*)&C[(long)r * ldc + col]       = make_float2(v0, v1);
            *(float2*)&C[(long)(r + 8) * ldc + col] = make_float2(v2, v3);
        }
    }
}

// ---------------- fused pair MLP (3xBF16, interleaved W2, LDS.64 B) -----------
#define PAIR_SMEM ((5120 + 33024 + 512) * 4)
__global__ __launch_bounds__(512, 1) void pair_mlp_mma(
    const float* __restrict__ UV, const float* __restrict__ b1,
    const uint32_t* __restrict__ W2p, const float* __restrict__ b2,
    const float* __restrict__ W3, const float* __restrict__ b3,
    float* __restrict__ Aout)
{
    extern __shared__ __align__(16) uint32_t sm[];
    uint32_t* As = sm;
    uint32_t* Bs = sm + 5120;
    float* wpart = (float*)(sm + 5120 + 33024);

    const int t = threadIdx.x, lane = t & 31, warp = t >> 5;
    const int gid = lane >> 2, tig = lane & 3;
    const int wm = warp >> 3, wn = warp & 7;
    const int m0 = wm * 32, n0w = wn * 64;
    const int bi = blockIdx.y;
    const long PK2 = 512L * 512;

    const int lr = t >> 3, k4 = (t & 7) * 4;
    const int mld = blockIdx.x * 64 + lr;
    const int valid = (mld < MM);
    int xl = 0, yl = 0;
    if (valid) { xl = mld / 63; int rl = mld - 63 * xl; yl = rl + (rl >= xl ? 1 : 0); }
    const float* Urow = UV + ((long)(bi * 64 + xl)) * 2048;
    const float* Vrow = UV + ((long)(bi * 64 + yl)) * 2048 + 1024;

    float4 ru, rv, rb;
    auto ldgA = [&](int k0) {
        ru = *(const float4*)(Urow + k0 + k4);
        rv = *(const float4*)(Vrow + k0 + k4);
        rb = *(const float4*)(b1 + k0 + k4);
    };
    auto stsA = [&](int buf) {
        float4 h;
        h.x = fmaxf(ru.x + rv.x + rb.x, 0.f);
        h.y = fmaxf(ru.y + rv.y + rb.y, 0.f);
        h.z = fmaxf(ru.z + rv.z + rb.z, 0.f);
        h.w = fmaxf(ru.w + rv.w + rb.w, 0.f);
        if (!valid) h = make_float4(0.f, 0.f, 0.f, 0.f);
        uint32_t* Ah = As + buf * 2560 + lr * 20;
        uint32_t* Al = Ah + 1280;
        const int w = (t & 7) * 2;
        uint32_t h0 = pk_hi(h.x, h.y), h1 = pk_hi(h.z, h.w);
        Ah[w] = h0; Ah[w + 1] = h1;
        Al[w]     = pk_lo(h.x, h.y, h0);
        Al[w + 1] = pk_lo(h.z, h.w, h1);
    };
    auto stageB = [&](int buf, int k0) {
        const int gr0 = k0 >> 2;
#pragma unroll
        for (int i = 0; i < 8; i++) {
            int f = t + i * 512;
            int plane = f >> 11, g = f & 2047;
            int rl = g >> 8, c4 = (g & 255) * 4;
            cpa16(&Bs[buf * 16512 + plane * 8256 + rl * 1032 + c4],
                  W2p + plane * PK2 + (long)(gr0 + rl) * 1024 + c4);
        }
        cp_commit();
    };

    float c[2][8][4];
#pragma unroll
    for (int mt = 0; mt < 2; mt++)
#pragma unroll
        for (int nt = 0; nt < 8; nt++)
#pragma unroll
            for (int e = 0; e < 4; e++) c[mt][nt][e] = 0.f;

    ldgA(0); stageB(0, 0); stsA(0);
    int buf = 0;
    for (int k0 = 0; k0 < REP; k0 += 32) {
        const bool more = (k0 + 32 < REP);
        cp_wait<0>();
        __syncthreads();
        if (more) { ldgA(k0 + 32); stageB(buf ^ 1, k0 + 32); }

        const uint32_t* Ah = As + buf * 2560;
        const uint32_t* Al = Ah + 1280;
        const uint32_t* Bh = Bs + buf * 16512;
        const uint32_t* Bl = Bh + 8256;
#pragma unroll
        for (int k16 = 0; k16 < 2; k16++) {
            const int kb = k16 * 8;
            uint32_t ah[2][4], al[2][4];
#pragma unroll
            for (int mt = 0; mt < 2; mt++) {
                int r0 = (m0 + mt * 16 + gid) * 20;
                int r1 = r0 + 160;
                ah[mt][0] = Ah[r0 + kb + tig];
                ah[mt][1] = Ah[r1 + kb + tig];
                ah[mt][2] = Ah[r0 + kb + tig + 4];
                ah[mt][3] = Ah[r1 + kb + tig + 4];
                al[mt][0] = Al[r0 + kb + tig];
                al[mt][1] = Al[r1 + kb + tig];
                al[mt][2] = Al[r0 + kb + tig + 4];
                al[mt][3] = Al[r1 + kb + tig + 4];
            }
            const int brow = (k16 * 4 + tig) * 1032;
#pragma unroll
            for (int nt = 0; nt < 8; nt++) {
                int cw = brow + 2 * (n0w + nt * 8 + gid);
                uint2 b2h = *(const uint2*)&Bh[cw];
                uint2 b2l = *(const uint2*)&Bl[cw];
                uint32_t bh[2] = { b2h.x, b2h.y };
                uint32_t bl[2] = { b2l.x, b2l.y };
#pragma unroll
                for (int mt = 0; mt < 2; mt++) {
                    mma16(c[mt][nt], ah[mt], bh);
                    mma16(c[mt][nt], ah[mt], bl);
                    mma16(c[mt][nt], al[mt], bh);
                }
            }
        }
        if (more) stsA(buf ^ 1);
        buf ^= 1;
    }

    float rp[4] = { 0.f, 0.f, 0.f, 0.f };
#pragma unroll
    for (int mt = 0; mt < 2; mt++) {
#pragma unroll
        for (int nt = 0; nt < 8; nt++) {
            int col = n0w + nt * 8 + 2 * tig;
            float b2a = b2[col], b2b = b2[col + 1];
            float w3a = W3[col], w3b = W3[col + 1];
            rp[2 * mt + 0] += fmaxf(c[mt][nt][0] + b2a, 0.f) * w3a
                            + fmaxf(c[mt][nt][1] + b2b, 0.f) * w3b;
            rp[2 * mt + 1] += fmaxf(c[mt][nt][2] + b2a, 0.f) * w3a
                            + fmaxf(c[mt][nt][3] + b2b, 0.f) * w3b;
        }
    }
#pragma unroll
    for (int e = 0; e < 4; e++) {
        float v = rp[e];
        v += __shfl_xor_sync(0xffffffffu, v, 1);
        v += __shfl_xor_sync(0xffffffffu, v, 2);
        int mt = e >> 1, o = e & 1;
        if (tig == 0) wpart[(m0 + mt * 16 + o * 8 + gid) * 8 + wn] = v;
    }
    __syncthreads();
    if (t < 64) {
        float s = b3[0];
#pragma unroll
        for (int w = 0; w < 8; w++) s += wpart[t * 8 + w];
        int m = blockIdx.x * 64 + t;
        if (m < MM) {
            int x = m / 63; int r = m - 63 * x; int y = r + (r >= x ? 1 : 0);
            Aout[(bi * 16 + x) * 64 + y] = 1.f / (1.f + expf(-s));
        }
    }
}

// ---------------- msg_h = A @ O ------------------------------------------------
__global__ __launch_bounds__(256) void msg_h_k(
    const float* __restrict__ Ag, const float* __restrict__ O, float* __restrict__ mh)
{
    __shared__ float As[NH * NN];
    const int b = blockIdx.y, t = threadIdx.x;
#pragma unroll
    for (int i = 0; i < 4; i++) As[t + 256 * i] = Ag[b * NH * NN + t + 256 * i];
    __syncthreads();
    const int j = blockIdx.x * 256 + t;
    float acc[NH];
#pragma unroll
    for (int x = 0; x < NH; x++) acc[x] = 0.f;
    for (int n = 0; n < NN; n++) {
        float o = O[((long)(b * NN + n)) * 1024 + j];
#pragma unroll
        for (int x = 0; x < NH; x++) acc[x] += As[x * NN + n] * o;
    }
#pragma unroll
    for (int x = 0; x < NH; x++) mh[((long)(b * NH + x)) * 1024 + j] = acc[x];
}

// ---------------- msg_o = A^T @ S ----------------------------------------------
__global__ __launch_bounds__(256) void msg_o_k(
    const float* __restrict__ Ag, const float* __restrict__ Sm, float* __restrict__ mo)
{
    __shared__ float As[NH * NN];
    const int b = blockIdx.y, t = threadIdx.x;
#pragma unroll
    for (int i = 0; i < 4; i++) As[t + 256 * i] = Ag[b * NH * NN + t + 256 * i];
    __syncthreads();
    const int j = blockIdx.x * 256 + t;
    float s[NH];
#pragma unroll
    for (int x = 0; x < NH; x++) s[x] = Sm[((long)(b * NH + x)) * 1024 + j];
    for (int n = 0; n < NN; n++) {
        float acc = 0.f;
#pragma unroll
        for (int x = 0; x < NH; x++) acc += As[x * NN + n] * s[x];
        mo[((long)(b * NN + n)) * 1024 + j] = acc;
    }
}

// ---------------- output assembly ----------------------------------------------
__device__ __forceinline__ float lis_f(float s) {
    return 8.3f / (1.f + expf(12.f - 10.f * s));
}

__global__ __launch_bounds__(128) void out_kernel(
    const float* __restrict__ enc, const float* __restrict__ Ag,
    const float* __restrict__ coords, const int* __restrict__ labels,
    const float* __restrict__ scores, float* __restrict__ out)
{
    const int b = blockIdx.y, m = blockIdx.x, t = threadIdx.x;
    const int x = m / 63; const int r = m - 63 * x; const int y = r + (r >= x ? 1 : 0);
    const long row = (long)b * MM + m;

    const float4* ex = (const float4*)(enc + ((long)(b * NN + x)) * RR);
    const float4* ey = (const float4*)(enc + ((long)(b * NN + y)) * RR);
    float4* po = (float4*)(out + row * 2048);
#pragma unroll
    for (int i = 0; i < 4; i++) {
        int q = t + (i << 7);
        po[q] = (q < 256) ? ex[q] : ey[q - 256];
    }
    if (t < 4)        out[OFF_BH + row * 4 + t]       = coords[(b * NN + x) * 4 + t];
    else if (t < 8)   out[OFF_BO + row * 4 + (t - 4)] = coords[(b * NN + y) * 4 + (t - 4)];

    const int lbl = labels[b * NN + y];
    const float val = Ag[(b * NH + x) * NN + y] *
                      lis_f(scores[b * NN + x]) * lis_f(scores[b * NN + y]);
    for (int c = t; c < NCLS; c += 128)
        out[OFF_PR + row * (long)NCLS + c] = (c == lbl) ? val : 0.f;
}

// ---------------- host orchestration -------------------------------------------
extern "C" void kernel_launch(void* const* d_in, const int* in_sizes, int n_in,
                              void* d_out, int out_size)
{
    const float* box_features = (const float*)d_in[0];
    const float* box_coords   = (const float*)d_in[1];
    const int*   box_labels   = (const int*)  d_in[2];
    const float* box_scores   = (const float*)d_in[3];
    const float* W1  = (const float*)d_in[4];
    const float* b1  = (const float*)d_in[5];
    const float* W2  = (const float*)d_in[6];
    const float* b2  = (const float*)d_in[7];
    const float* W3  = (const float*)d_in[8];
    const float* b3  = (const float*)d_in[9];
    const float* Ws  = (const float*)d_in[10];
    const float* bs  = (const float*)d_in[11];
    const float* Wo  = (const float*)d_in[12];
    const float* bo  = (const float*)d_in[13];
    const float* Wsu = (const float*)d_in[14];
    const float* Wou = (const float*)d_in[15];
    float* out = (float*)d_out;

    float *encA, *encB, *UV, *O, *mh, *eh, *Sb, *mo, *Ag;
    uint32_t *W1p, *W2p, *Wop, *Wsp, *Wsup, *Woup;
    cudaGetSymbolAddress((void**)&encA, g_encA);
    cudaGetSymbolAddress((void**)&encB, g_encB);
    cudaGetSymbolAddress((void**)&UV,   g_UV);
    cudaGetSymbolAddress((void**)&O,    g_O);
    cudaGetSymbolAddress((void**)&mh,   g_mh);
    cudaGetSymbolAddress((void**)&eh,   g_eh);
    cudaGetSymbolAddress((void**)&Sb,   g_S);
    cudaGetSymbolAddress((void**)&mo,   g_mo);
    cudaGetSymbolAddress((void**)&Ag,   g_A);
    cudaGetSymbolAddress((void**)&W1p,  g_W1p);
    cudaGetSymbolAddress((void**)&W2p,  g_W2p);
    cudaGetSymbolAddress((void**)&Wop,  g_Wop);
    cudaGetSymbolAddress((void**)&Wsp,  g_Wsp);
    cudaGetSymbolAddress((void**)&Wsup, g_Wsup);
    cudaGetSymbolAddress((void**)&Woup, g_Woup);

    cudaFuncSetAttribute(gemm_bf16p,
                         cudaFuncAttributeMaxDynamicSharedMemorySize, GEMM_SMEM);
    cudaFuncSetAttribute(pair_mlp_mma,
                         cudaFuncAttributeMaxDynamicSharedMemorySize, PAIR_SMEM);

    // aux stream + events (created per call; never destroyed during capture)
    cudaStream_t s1;
    cudaStreamCreateWithFlags(&s1, cudaStreamNonBlocking);
    cudaEvent_t ev[6];
    for (int i = 0; i < 6; i++)
        cudaEventCreateWithFlags(&ev[i], cudaEventDisableTiming);

    // ---- prepack, split across streams ----
    cudaEventRecord(ev[0], 0);
    cudaStreamWaitEvent(s1, ev[0], 0);
    // s0:
    pack_wuv<<<512, 256>>>(W1, W1p);
    pack_w<<<256, 256>>>(Wo,  Wop,  512, 1024);
    pack_w<<<512, 256>>>(Wsu, Wsup, 1024, 1024);
    // s1:
    pack_w<<<256, 256, 0, s1>>>(W2, W2p, 512, 512);
    pack_w<<<256, 256, 0, s1>>>(Ws, Wsp, 512, 1024);
    pack_w<<<512, 256, 0, s1>>>(Wou, Woup, 1024, 1024);
    cudaMemcpyAsync(encA, box_features, (size_t)BB * NN * RR * 4,
                    cudaMemcpyDeviceToDevice, s1);
    cudaEventRecord(ev[1], s1);
    cudaStreamWaitEvent(0, ev[1], 0);

    const long sEnc = (long)NN * RR;   // 65536
    const long sH   = (long)NH * RR;   // 16384
    const float* NUL = (const float*)0;

    for (int it = 0; it < 2; it++) {
        float* encIn  = (it == 0) ? encA : encB;
        float* encOut = (it == 0) ? encB : encA;
        cudaEvent_t evF = ev[2 + 2 * it], evJ = ev[3 + 2 * it];

        // fork: O gemm on s1 (depends only on encIn)
        cudaEventRecord(evF, 0);
        cudaStreamWaitEvent(s1, evF, 0);
        gemm_bf16p<<<dim3(8, 32), 256, GEMM_SMEM, s1>>>(
            encIn, NUL, 6, sEnc, 1024, NUL, 0,
            Wop, bo, O, 1024, 512L * 1024, 1024, 1024, 1);

        // s0: UV gemm -> pair MLP
        gemm_bf16p<<<dim3(16, 32), 256, GEMM_SMEM>>>(
            encIn, NUL, 6, sEnc, 1024, NUL, 0,
            W1p, NUL, UV, 2048, 512L * 2048, 2048, 1024, 0);
        pair_mlp_mma<<<dim3(16, BB), 512, PAIR_SMEM>>>(
            UV, b1, W2p, b2, W3, b3, Ag);

        // join before msg_h (needs A and O)
        cudaEventRecord(evJ, s1);
        cudaStreamWaitEvent(0, evJ, 0);

        msg_h_k<<<dim3(4, BB), 256>>>(Ag, O, mh);
        gemm_bf16p<<<dim3(8, 8), 256, GEMM_SMEM>>>(
            encIn, NUL, 4, sEnc, 1024, mh, sH,
            Wsup, NUL, eh, 1024, 1024L * 1024, 1024, 2048, 0);
        gemm_bf16p<<<dim3(8, 8), 256, GEMM_SMEM>>>(
            eh, NUL, 4, sH, 1024, NUL, 0,
            Wsp, bs, Sb, 1024, 512L * 1024, 1024, 1024, 1);
        msg_o_k<<<dim3(4, BB), 256>>>(Ag, Sb, mo);
        // splice handled via A1o override: rows n<16 read eh instead of encIn
        gemm_bf16p<<<dim3(8, 32), 256, GEMM_SMEM>>>(
            encIn, eh, 6, sEnc, 1024, mo, sEnc,
            Woup, NUL, encOut, 1024, 1024L * 1024, 1024, 2048, 0);
    }

    out_kernel<<<dim3(MM, BB), 128>>>(encA, Ag, box_coords, box_labels,
                                      box_scores, out);
    (void)in_sizes; (void)n_in; (void)out_size;
}

// round 11
// speedup vs baseline: 2.6384x; 1.2189x over previous
#include <cuda_runtime.h>
#include <cuda_fp16.h>
#include <math.h>
#include <stdint.h>

// Problem constants
#define BB   32
#define NN   64
#define NH   16
#define RR   1024
#define REP  1024
#define MM   1008
#define NCLS 117

// Output layout offsets (floats)
#define OFF_BH  66060288L
#define OFF_BO  66189312L
#define OFF_PR  66318336L

// ---------------- scratch (device globals) -----------------------------------
__device__ float g_encA[BB * NN * RR];
__device__ float g_encB[BB * NN * RR];
__device__ float g_UV [BB * NN * 2048];
__device__ float g_O  [BB * NN * REP];
__device__ float g_mh [BB * NH * REP];
__device__ float g_eh [BB * NH * RR];
__device__ float g_S  [BB * NH * REP];
__device__ float g_mo [BB * NN * REP];
__device__ float g_A  [BB * NH * NN];

// packed weights, interleaved-pair layout, fp16 hi/lo planes
__device__ uint32_t g_W1p [1024L * 2048];
__device__ uint32_t g_W2p [1024L * 512];
__device__ uint32_t g_Wop [1024L * 1024];
__device__ uint32_t g_Wsp [1024L * 1024];
__device__ uint32_t g_Wsup[2048L * 1024];
__device__ uint32_t g_Woup[2048L * 1024];

// ---------------- helpers ----------------------------------------------------
// fp16 m16n8k16 MMA, fp32 accum
__device__ __forceinline__ void mma16(float* c, const uint32_t* a, const uint32_t* b)
{
    asm volatile(
        "mma.sync.aligned.m16n8k16.row.col.f32.f16.f16.f32 "
        "{%0,%1,%2,%3}, {%4,%5,%6,%7}, {%8,%9}, {%0,%1,%2,%3};\n"
        : "+f"(c[0]), "+f"(c[1]), "+f"(c[2]), "+f"(c[3])
        : "r"(a[0]), "r"(a[1]), "r"(a[2]), "r"(a[3]), "r"(b[0]), "r"(b[1]));
}

// pack two fp32 into f16x2 (x0 -> low half = lower k index)
__device__ __forceinline__ uint32_t pk_hi(float x0, float x1)
{
    uint32_t r;
    asm("cvt.rn.f16x2.f32 %0, %1, %2;" : "=r"(r) : "f"(x1), "f"(x0));
    return r;
}
// residual (x - hi) packed to f16x2
__device__ __forceinline__ uint32_t pk_lo(float x0, float x1, uint32_t hi)
{
    __half2 h = *reinterpret_cast<__half2*>(&hi);
    float l0 = x0 - __low2float(h);
    float l1 = x1 - __high2float(h);
    return pk_hi(l0, l1);
}

__device__ __forceinline__ void cpa16(void* smem, const void* gmem)
{
    uint32_t s = (uint32_t)__cvta_generic_to_shared(smem);
    asm volatile("cp.async.cg.shared.global [%0], [%1], 16;\n" :: "r"(s), "l"(gmem));
}
__device__ __forceinline__ void cp_commit()
{
    asm volatile("cp.async.commit_group;\n");
}
template <int N> __device__ __forceinline__ void cp_wait()
{
    asm volatile("cp.async.wait_group %0;\n" :: "n"(N));
}

// ---------------- weight prepack (interleaved-pair layout, fp16 planes) -------
__global__ __launch_bounds__(256) void pack_w(
    const float* __restrict__ W, uint32_t* __restrict__ Wp, int Kh, int N)
{
    const long plane = (long)Kh * N;
    const long total = 2 * plane;
    const int rowlen = 2 * N;
    for (long i = blockIdx.x * blockDim.x + threadIdx.x; i < total;
         i += (long)gridDim.x * blockDim.x) {
        int p = (int)(i / plane);
        long rem = i - (long)p * plane;
        int row = (int)(rem / rowlen);
        int col2 = (int)(rem - (long)row * rowlen);
        int n = col2 >> 1, j = col2 & 1;
        int q = row >> 2, tig = row & 3;
        int kp = q * 8 + tig + 4 * j;
        float x0 = W[(long)(2 * kp) * N + n];
        float x1 = W[(long)(2 * kp + 1) * N + n];
        uint32_t hi = pk_hi(x0, x1);
        Wp[i] = p ? pk_lo(x0, x1, hi) : hi;
    }
}

// fused UV pack: Wuv(k, c) = c<1024 ? W1[k][c] : W1[1024+k][c-1024]
__global__ __launch_bounds__(256) void pack_wuv(
    const float* __restrict__ W1, uint32_t* __restrict__ Wp)
{
    const long plane = 512L * 2048;
    const long total = 2 * plane;
    for (long i = blockIdx.x * blockDim.x + threadIdx.x; i < total;
         i += (long)gridDim.x * blockDim.x) {
        int p = (int)(i / plane);
        long rem = i - (long)p * plane;
        int row = (int)(rem >> 12);
        int col2 = (int)(rem & 4095);
        int n = col2 >> 1, j = col2 & 1;
        int q = row >> 2, tig = row & 3;
        int kp = q * 8 + tig + 4 * j;
        int k0 = 2 * kp, k1 = 2 * kp + 1;
        float x0, x1;
        if (n < 1024) {
            x0 = W1[(long)k0 * 1024 + n];
            x1 = W1[(long)k1 * 1024 + n];
        } else {
            x0 = W1[(long)(1024 + k0) * 1024 + (n - 1024)];
            x1 = W1[(long)(1024 + k1) * 1024 + (n - 1024)];
        }
        uint32_t hi = pk_hi(x0, x1);
        Wp[i] = p ? pk_lo(x0, x1, hi) : hi;
    }
}

// ---------------- batched GEMM (fp16 2-product, interleaved W) ----------------
// D = fp16(A) @ (Whi + Wlo). A single plane; W hi/lo planes.
// smem: A [2][64][20] = 2560 w; B [2][2][8][264] = 8448 w.
#define GEMM_SMEM ((2560 + 8448) * 4)
__global__ __launch_bounds__(256, 2) void gemm_f16p(
    const float* __restrict__ A1, const float* __restrict__ A1o,
    int lrpb, long sA1, int K1,
    const float* __restrict__ A2, long sA2,
    const uint32_t* __restrict__ Wp, const float* __restrict__ bias,
    float* __restrict__ C, int Nw, long PKw, int ldc, int Ktot, int do_relu)
{
    extern __shared__ __align__(16) uint32_t sm[];
    uint32_t* As = sm;          // single A plane, double-buffered
    uint32_t* Bs = sm + 2560;

    const int t = threadIdx.x, lane = t & 31, warp = t >> 5;
    const int gid = lane >> 2, tig = lane & 3;
    const int wm = warp >> 2, wn = warp & 3;
    const int m0 = wm * 32, n0w = wn * 32;
    const long bn0 = (long)blockIdx.x * 128;
    const int bm0 = blockIdx.y * 64;
    const int K2 = Ktot - K1;
    const int rmask = (1 << lrpb) - 1;

    const int lrow = t >> 2, lf4 = t & 3;
    const int grow = bm0 + lrow;
    const int b = grow >> lrpb, n = grow & rmask;
    const float* p1 = (A1o && n < 16)
                        ? (A1o + (long)b * 16384 + (long)n * 1024)
                        : (A1 + (long)b * sA1 + (long)n * K1);
    const float* p2 = A2 ? (A2 + (long)b * sA2 + (long)n * K2) : p1;

    float4 ra0, ra1;
    auto ldgA = [&](int k0) {
        const float* rp = (k0 < K1) ? (p1 + k0) : (p2 + (k0 - K1));
        ra0 = *(const float4*)(rp + lf4 * 4);
        ra1 = *(const float4*)(rp + lf4 * 4 + 16);
    };
    auto stsA = [&](int buf) {
        uint32_t* Ah = As + buf * 1280 + lrow * 20;
        const int w = lf4 * 2;
        Ah[w]     = pk_hi(ra0.x, ra0.y);
        Ah[w + 1] = pk_hi(ra0.z, ra0.w);
        Ah[w + 8] = pk_hi(ra1.x, ra1.y);
        Ah[w + 9] = pk_hi(ra1.z, ra1.w);
    };
    auto stageB = [&](int buf, int k0) {
        const int gr0 = k0 >> 2;
#pragma unroll
        for (int i = 0; i < 4; i++) {
            int f = t + i * 256;
            int plane = f >> 9, g = f & 511;
            int rl = g >> 6, c4 = (g & 63) * 4;
            cpa16(&Bs[buf * 4224 + plane * 2112 + rl * 264 + c4],
                  Wp + plane * PKw + (long)(gr0 + rl) * (2 * Nw) + bn0 * 2 + c4);
        }
        cp_commit();
    };

    float c[2][4][4];
#pragma unroll
    for (int mt = 0; mt < 2; mt++)
#pragma unroll
        for (int nt = 0; nt < 4; nt++)
#pragma unroll
            for (int e = 0; e < 4; e++) c[mt][nt][e] = 0.f;

    ldgA(0); stageB(0, 0); stsA(0);
    int buf = 0;
    for (int k0 = 0; k0 < Ktot; k0 += 32) {
        const bool more = (k0 + 32 < Ktot);
        cp_wait<0>();
        __syncthreads();
        if (more) { ldgA(k0 + 32); stageB(buf ^ 1, k0 + 32); }

        const uint32_t* Ah = As + buf * 1280;
        const uint32_t* Bh = Bs + buf * 4224;
        const uint32_t* Bl = Bh + 2112;
#pragma unroll
        for (int k16 = 0; k16 < 2; k16++) {
            const int kb = k16 * 8;
            uint32_t ah[2][4];
#pragma unroll
            for (int mt = 0; mt < 2; mt++) {
                int r0 = (m0 + mt * 16 + gid) * 20;
                int r1 = r0 + 160;
                ah[mt][0] = Ah[r0 + kb + tig];
                ah[mt][1] = Ah[r1 + kb + tig];
                ah[mt][2] = Ah[r0 + kb + tig + 4];
                ah[mt][3] = Ah[r1 + kb + tig + 4];
            }
            const int brow = (k16 * 4 + tig) * 264;
#pragma unroll
            for (int nt = 0; nt < 4; nt++) {
                int cw = brow + 2 * (n0w + nt * 8 + gid);
                uint2 b2h = *(const uint2*)&Bh[cw];
                uint2 b2l = *(const uint2*)&Bl[cw];
                uint32_t bh[2] = { b2h.x, b2h.y };
                uint32_t bl[2] = { b2l.x, b2l.y };
#pragma unroll
                for (int mt = 0; mt < 2; mt++) {
                    mma16(c[mt][nt], ah[mt], bh);
                    mma16(c[mt][nt], ah[mt], bl);
                }
            }
        }
        if (more) stsA(buf ^ 1);
        buf ^= 1;
    }

#pragma unroll
    for (int mt = 0; mt < 2; mt++) {
#pragma unroll
        for (int nt = 0; nt < 4; nt++) {
            long col = bn0 + n0w + nt * 8 + 2 * tig;
            float b0v = 0.f, b1v = 0.f;
            if (bias) { b0v = bias[col]; b1v = bias[col + 1]; }
            int r = bm0 + m0 + mt * 16 + gid;
            float v0 = c[mt][nt][0] + b0v, v1 = c[mt][nt][1] + b1v;
            float v2 = c[mt][nt][2] + b0v, v3 = c[mt][nt][3] + b1v;
            if (do_relu) {
                v0 = fmaxf(v0, 0.f); v1 = fmaxf(v1, 0.f);
                v2 = fmaxf(v2, 0.f); v3 = fmaxf(v3, 0.f);
            }
            *(float2*)&C[(long)r * ldc + col]       = make_float2(v0, v1);
            *(float2*)&C[(long)(r + 8) * ldc + col] = make_float2(v2, v3);
        }
    }
}

// ---------------- fused pair MLP (fp16 2-product, interleaved W2) -------------
// smem: A [2][64][20] = 2560 w; B [2][2][8][1032] = 33024 w; wpart 512 w.
#define PAIR_SMEM ((2560 + 33024 + 512) * 4)
__global__ __launch_bounds__(512, 1) void pair_mlp_mma(
    const float* __restrict__ UV, const float* __restrict__ b1,
    const uint32_t* __restrict__ W2p, const float* __restrict__ b2,
    const float* __restrict__ W3, const float* __restrict__ b3,
    float* __restrict__ Aout)
{
    extern __shared__ __align__(16) uint32_t sm[];
    uint32_t* As = sm;
    uint32_t* Bs = sm + 2560;
    float* wpart = (float*)(sm + 2560 + 33024);

    const int t = threadIdx.x, lane = t & 31, warp = t >> 5;
    const int gid = lane >> 2, tig = lane & 3;
    const int wm = warp >> 3, wn = warp & 7;
    const int m0 = wm * 32, n0w = wn * 64;
    const int bi = blockIdx.y;
    const long PK2 = 512L * 512;

    const int lr = t >> 3, k4 = (t & 7) * 4;
    const int mld = blockIdx.x * 64 + lr;
    const int valid = (mld < MM);
    int xl = 0, yl = 0;
    if (valid) { xl = mld / 63; int rl = mld - 63 * xl; yl = rl + (rl >= xl ? 1 : 0); }
    const float* Urow = UV + ((long)(bi * 64 + xl)) * 2048;
    const float* Vrow = UV + ((long)(bi * 64 + yl)) * 2048 + 1024;

    float4 ru, rv, rb;
    auto ldgA = [&](int k0) {
        ru = *(const float4*)(Urow + k0 + k4);
        rv = *(const float4*)(Vrow + k0 + k4);
        rb = *(const float4*)(b1 + k0 + k4);
    };
    auto stsA = [&](int buf) {
        float4 h;
        h.x = fmaxf(ru.x + rv.x + rb.x, 0.f);
        h.y = fmaxf(ru.y + rv.y + rb.y, 0.f);
        h.z = fmaxf(ru.z + rv.z + rb.z, 0.f);
        h.w = fmaxf(ru.w + rv.w + rb.w, 0.f);
        if (!valid) h = make_float4(0.f, 0.f, 0.f, 0.f);
        uint32_t* Ah = As + buf * 1280 + lr * 20;
        const int w = (t & 7) * 2;
        Ah[w]     = pk_hi(h.x, h.y);
        Ah[w + 1] = pk_hi(h.z, h.w);
    };
    auto stageB = [&](int buf, int k0) {
        const int gr0 = k0 >> 2;
#pragma unroll
        for (int i = 0; i < 8; i++) {
            int f = t + i * 512;
            int plane = f >> 11, g = f & 2047;
            int rl = g >> 8, c4 = (g & 255) * 4;
            cpa16(&Bs[buf * 16512 + plane * 8256 + rl * 1032 + c4],
                  W2p + plane * PK2 + (long)(gr0 + rl) * 1024 + c4);
        }
        cp_commit();
    };

    float c[2][8][4];
#pragma unroll
    for (int mt = 0; mt < 2; mt++)
#pragma unroll
        for (int nt = 0; nt < 8; nt++)
#pragma unroll
            for (int e = 0; e < 4; e++) c[mt][nt][e] = 0.f;

    ldgA(0); stageB(0, 0); stsA(0);
    int buf = 0;
    for (int k0 = 0; k0 < REP; k0 += 32) {
        const bool more = (k0 + 32 < REP);
        cp_wait<0>();
        __syncthreads();
        if (more) { ldgA(k0 + 32); stageB(buf ^ 1, k0 + 32); }

        const uint32_t* Ah = As + buf * 1280;
        const uint32_t* Bh = Bs + buf * 16512;
        const uint32_t* Bl = Bh + 8256;
#pragma unroll
        for (int k16 = 0; k16 < 2; k16++) {
            const int kb = k16 * 8;
            uint32_t ah[2][4];
#pragma unroll
            for (int mt = 0; mt < 2; mt++) {
                int r0 = (m0 + mt * 16 + gid) * 20;
                int r1 = r0 + 160;
                ah[mt][0] = Ah[r0 + kb + tig];
                ah[mt][1] = Ah[r1 + kb + tig];
                ah[mt][2] = Ah[r0 + kb + tig + 4];
                ah[mt][3] = Ah[r1 + kb + tig + 4];
            }
            const int brow = (k16 * 4 + tig) * 1032;
#pragma unroll
            for (int nt = 0; nt < 8; nt++) {
                int cw = brow + 2 * (n0w + nt * 8 + gid);
                uint2 b2h = *(const uint2*)&Bh[cw];
                uint2 b2l = *(const uint2*)&Bl[cw];
                uint32_t bh[2] = { b2h.x, b2h.y };
                uint32_t bl[2] = { b2l.x, b2l.y };
#pragma unroll
                for (int mt = 0; mt < 2; mt++) {
                    mma16(c[mt][nt], ah[mt], bh);
                    mma16(c[mt][nt], ah[mt], bl);
                }
            }
        }
        if (more) stsA(buf ^ 1);
        buf ^= 1;
    }

    float rp[4] = { 0.f, 0.f, 0.f, 0.f };
#pragma unroll
    for (int mt = 0; mt < 2; mt++) {
#pragma unroll
        for (int nt = 0; nt < 8; nt++) {
            int col = n0w + nt * 8 + 2 * tig;
            float b2a = b2[col], b2b = b2[col + 1];
            float w3a = W3[col], w3b = W3[col + 1];
            rp[2 * mt + 0] += fmaxf(c[mt][nt][0] + b2a, 0.f) * w3a
                            + fmaxf(c[mt][nt][1] + b2b, 0.f) * w3b;
            rp[2 * mt + 1] += fmaxf(c[mt][nt][2] + b2a, 0.f) * w3a
                            + fmaxf(c[mt][nt][3] + b2b, 0.f) * w3b;
        }
    }
#pragma unroll
    for (int e = 0; e < 4; e++) {
        float v = rp[e];
        v += __shfl_xor_sync(0xffffffffu, v, 1);
        v += __shfl_xor_sync(0xffffffffu, v, 2);
        int mt = e >> 1, o = e & 1;
        if (tig == 0) wpart[(m0 + mt * 16 + o * 8 + gid) * 8 + wn] = v;
    }
    __syncthreads();
    if (t < 64) {
        float s = b3[0];
#pragma unroll
        for (int w = 0; w < 8; w++) s += wpart[t * 8 + w];
        int m = blockIdx.x * 64 + t;
        if (m < MM) {
            int x = m / 63; int r = m - 63 * x; int y = r + (r >= x ? 1 : 0);
            Aout[(bi * 16 + x) * 64 + y] = 1.f / (1.f + expf(-s));
        }
    }
}

// ---------------- msg_h = A @ O ------------------------------------------------
__global__ __launch_bounds__(256) void msg_h_k(
    const float* __restrict__ Ag, const float* __restrict__ O, float* __restrict__ mh)
{
    __shared__ float As[NH * NN];
    const int b = blockIdx.y, t = threadIdx.x;
#pragma unroll
    for (int i = 0; i < 4; i++) As[t + 256 * i] = Ag[b * NH * NN + t + 256 * i];
    __syncthreads();
    const int j = blockIdx.x * 256 + t;
    float acc[NH];
#pragma unroll
    for (int x = 0; x < NH; x++) acc[x] = 0.f;
    for (int n = 0; n < NN; n++) {
        float o = O[((long)(b * NN + n)) * 1024 + j];
#pragma unroll
        for (int x = 0; x < NH; x++) acc[x] += As[x * NN + n] * o;
    }
#pragma unroll
    for (int x = 0; x < NH; x++) mh[((long)(b * NH + x)) * 1024 + j] = acc[x];
}

// ---------------- msg_o = A^T @ S ----------------------------------------------
__global__ __launch_bounds__(256) void msg_o_k(
    const float* __restrict__ Ag, const float* __restrict__ Sm, float* __restrict__ mo)
{
    __shared__ float As[NH * NN];
    const int b = blockIdx.y, t = threadIdx.x;
#pragma unroll
    for (int i = 0; i < 4; i++) As[t + 256 * i] = Ag[b * NH * NN + t + 256 * i];
    __syncthreads();
    const int j = blockIdx.x * 256 + t;
    float s[NH];
#pragma unroll
    for (int x = 0; x < NH; x++) s[x] = Sm[((long)(b * NH + x)) * 1024 + j];
    for (int n = 0; n < NN; n++) {
        float acc = 0.f;
#pragma unroll
        for (int x = 0; x < NH; x++) acc += As[x * NN + n] * s[x];
        mo[((long)(b * NN + n)) * 1024 + j] = acc;
    }
}

// ---------------- output assembly ----------------------------------------------
__device__ __forceinline__ float lis_f(float s) {
    return 8.3f / (1.f + expf(12.f - 10.f * s));
}

__global__ __launch_bounds__(128) void out_kernel(
    const float* __restrict__ enc, const float* __restrict__ Ag,
    const float* __restrict__ coords, const int* __restrict__ labels,
    const float* __restrict__ scores, float* __restrict__ out)
{
    const int b = blockIdx.y, m = blockIdx.x, t = threadIdx.x;
    const int x = m / 63; const int r = m - 63 * x; const int y = r + (r >= x ? 1 : 0);
    const long row = (long)b * MM + m;

    const float4* ex = (const float4*)(enc + ((long)(b * NN + x)) * RR);
    const float4* ey = (const float4*)(enc + ((long)(b * NN + y)) * RR);
    float4* po = (float4*)(out + row * 2048);
#pragma unroll
    for (int i = 0; i < 4; i++) {
        int q = t + (i << 7);
        po[q] = (q < 256) ? ex[q] : ey[q - 256];
    }
    if (t < 4)        out[OFF_BH + row * 4 + t]       = coords[(b * NN + x) * 4 + t];
    else if (t < 8)   out[OFF_BO + row * 4 + (t - 4)] = coords[(b * NN + y) * 4 + (t - 4)];

    const int lbl = labels[b * NN + y];
    const float val = Ag[(b * NH + x) * NN + y] *
                      lis_f(scores[b * NN + x]) * lis_f(scores[b * NN + y]);
    for (int c = t; c < NCLS; c += 128)
        out[OFF_PR + row * (long)NCLS + c] = (c == lbl) ? val : 0.f;
}

// ---------------- host orchestration -------------------------------------------
extern "C" void kernel_launch(void* const* d_in, const int* in_sizes, int n_in,
                              void* d_out, int out_size)
{
    const float* box_features = (const float*)d_in[0];
    const float* box_coords   = (const float*)d_in[1];
    const int*   box_labels   = (const int*)  d_in[2];
    const float* box_scores   = (const float*)d_in[3];
    const float* W1  = (const float*)d_in[4];
    const float* b1  = (const float*)d_in[5];
    const float* W2  = (const float*)d_in[6];
    const float* b2  = (const float*)d_in[7];
    const float* W3  = (const float*)d_in[8];
    const float* b3  = (const float*)d_in[9];
    const float* Ws  = (const float*)d_in[10];
    const float* bs  = (const float*)d_in[11];
    const float* Wo  = (const float*)d_in[12];
    const float* bo  = (const float*)d_in[13];
    const float* Wsu = (const float*)d_in[14];
    const float* Wou = (const float*)d_in[15];
    float* out = (float*)d_out;

    float *encA, *encB, *UV, *O, *mh, *eh, *Sb, *mo, *Ag;
    uint32_t *W1p, *W2p, *Wop, *Wsp, *Wsup, *Woup;
    cudaGetSymbolAddress((void**)&encA, g_encA);
    cudaGetSymbolAddress((void**)&encB, g_encB);
    cudaGetSymbolAddress((void**)&UV,   g_UV);
    cudaGetSymbolAddress((void**)&O,    g_O);
    cudaGetSymbolAddress((void**)&mh,   g_mh);
    cudaGetSymbolAddress((void**)&eh,   g_eh);
    cudaGetSymbolAddress((void**)&Sb,   g_S);
    cudaGetSymbolAddress((void**)&mo,   g_mo);
    cudaGetSymbolAddress((void**)&Ag,   g_A);
    cudaGetSymbolAddress((void**)&W1p,  g_W1p);
    cudaGetSymbolAddress((void**)&W2p,  g_W2p);
    cudaGetSymbolAddress((void**)&Wop,  g_Wop);
    cudaGetSymbolAddress((void**)&Wsp,  g_Wsp);
    cudaGetSymbolAddress((void**)&Wsup, g_Wsup);
    cudaGetSymbolAddress((void**)&Woup, g_Woup);

    cudaFuncSetAttribute(gemm_f16p,
                         cudaFuncAttributeMaxDynamicSharedMemorySize, GEMM_SMEM);
    cudaFuncSetAttribute(pair_mlp_mma,
                         cudaFuncAttributeMaxDynamicSharedMemorySize, PAIR_SMEM);

    // aux stream + events (created per call; never destroyed during capture)
    cudaStream_t s1;
    cudaStreamCreateWithFlags(&s1, cudaStreamNonBlocking);
    cudaEvent_t ev[6];
    for (int i = 0; i < 6; i++)
        cudaEventCreateWithFlags(&ev[i], cudaEventDisableTiming);

    // ---- prepack, split across streams ----
    cudaEventRecord(ev[0], 0);
    cudaStreamWaitEvent(s1, ev[0], 0);
    pack_wuv<<<512, 256>>>(W1, W1p);
    pack_w<<<256, 256>>>(Wo,  Wop,  512, 1024);
    pack_w<<<512, 256>>>(Wsu, Wsup, 1024, 1024);
    pack_w<<<256, 256, 0, s1>>>(W2, W2p, 512, 512);
    pack_w<<<256, 256, 0, s1>>>(Ws, Wsp, 512, 1024);
    pack_w<<<512, 256, 0, s1>>>(Wou, Woup, 1024, 1024);
    cudaMemcpyAsync(encA, box_features, (size_t)BB * NN * RR * 4,
                    cudaMemcpyDeviceToDevice, s1);
    cudaEventRecord(ev[1], s1);
    cudaStreamWaitEvent(0, ev[1], 0);

    const long sEnc = (long)NN * RR;   // 65536
    const long sH   = (long)NH * RR;   // 16384
    const float* NUL = (const float*)0;

    for (int it = 0; it < 2; it++) {
        float* encIn  = (it == 0) ? encA : encB;
        float* encOut = (it == 0) ? encB : encA;
        cudaEvent_t evF = ev[2 + 2 * it], evJ = ev[3 + 2 * it];

        // fork: O gemm on s1 (depends only on encIn)
        cudaEventRecord(evF, 0);
        cudaStreamWaitEvent(s1, evF, 0);
        gemm_f16p<<<dim3(8, 32), 256, GEMM_SMEM, s1>>>(
            encIn, NUL, 6, sEnc, 1024, NUL, 0,
            Wop, bo, O, 1024, 512L * 1024, 1024, 1024, 1);

        // s0: UV gemm -> pair MLP
        gemm_f16p<<<dim3(16, 32), 256, GEMM_SMEM>>>(
            encIn, NUL, 6, sEnc, 1024, NUL, 0,
            W1p, NUL, UV, 2048, 512L * 2048, 2048, 1024, 0);
        pair_mlp_mma<<<dim3(16, BB), 512, PAIR_SMEM>>>(
            UV, b1, W2p, b2, W3, b3, Ag);

        // join before msg_h (needs A and O)
        cudaEventRecord(evJ, s1);
        cudaStreamWaitEvent(0, evJ, 0);

        msg_h_k<<<dim3(4, BB), 256>>>(Ag, O, mh);
        gemm_f16p<<<dim3(8, 8), 256, GEMM_SMEM>>>(
            encIn, NUL, 4, sEnc, 1024, mh, sH,
            Wsup, NUL, eh, 1024, 1024L * 1024, 1024, 2048, 0);
        gemm_f16p<<<dim3(8, 8), 256, GEMM_SMEM>>>(
            eh, NUL, 4, sH, 1024, NUL, 0,
            Wsp, bs, Sb, 1024, 512L * 1024, 1024, 1024, 1);
        msg_o_k<<<dim3(4, BB), 256>>>(Ag, Sb, mo);
        // splice handled via A1o override: rows n<16 read eh instead of encIn
        gemm_f16p<<<dim3(8, 32), 256, GEMM_SMEM>>>(
            encIn, eh, 6, sEnc, 1024, mo, sEnc,
            Woup, NUL, encOut, 1024, 1024L * 1024, 1024, 2048, 0);
    }

    out_kernel<<<dim3(MM, BB), 128>>>(encA, Ag, box_coords, box_labels,
                                      box_scores, out);
    (void)in_sizes; (void)n_in; (void)out_size;
}